// round 1
// baseline (speedup 1.0000x reference)
#include <cuda_runtime.h>
#include <math.h>

// ---------------------------------------------------------------------------
// Problem dimensions (fixed by the dataset)
// ---------------------------------------------------------------------------
#define BB   16
#define TT   1500
#define DD   1024
#define DH   1023          // D-1 hidden dim fed to CIF
#define DTXT 4096
#define NTOK 375
#define MM   (BB*NTOK)     // 6000 rows
#define MAXP 12288         // max CIF pairs per batch (worst case ~3000)

// ---------------------------------------------------------------------------
// Device scratch (allocation-free rule: __device__ globals)
// ---------------------------------------------------------------------------
__device__ float g_alphas[BB*TT];
__device__ float g_numpred[BB];
__device__ int   g_nf[BB];
__device__ int   g_nt[BB];
__device__ int   g_pair_n[BB*MAXP];
__device__ int   g_pair_t[BB*MAXP];
__device__ float g_pair_w[BB*MAXP];
__device__ int   g_rowptr[BB*(NTOK+1)];
__device__ float g_h1[(size_t)MM*DH];   // CIF output  [B,N,DH]
__device__ float g_h2[(size_t)MM*DD];   // cif_proj out / rmsnorm in-place

// ---------------------------------------------------------------------------
// Kernel 0: detect int64 vs int32 for num_frames / num_text_tokens and
// normalize to int32. num_frames[1] in [800,1500] so its int32 word != 0;
// under int64 little-endian the second 32-bit word is the high word == 0.
// Only the first 64 bytes are read before the width is decided.
// ---------------------------------------------------------------------------
__global__ void k_detect(const void* nf_raw, const void* nt_raw) {
    const int* a = (const int*)nf_raw;
    const int* b = (const int*)nt_raw;
    bool is64 = (a[1] == 0);
    for (int i = 0; i < BB; i++) {
        if (is64) {
            g_nf[i] = (int)((const long long*)nf_raw)[i];
            g_nt[i] = (int)((const long long*)nt_raw)[i];
        } else {
            g_nf[i] = a[i];
            g_nt[i] = b[i];
        }
    }
}

// ---------------------------------------------------------------------------
// Kernel 1: masked sigmoid, per-batch sum, scale, write scaled alphas.
// One block per batch.
// ---------------------------------------------------------------------------
__global__ void k_alphas(const float* __restrict__ af) {
    int b = blockIdx.x;
    __shared__ float sh[TT];
    __shared__ float red[256];
    int nf = g_nf[b];
    float s = 0.f;
    for (int t = threadIdx.x; t < TT; t += 256) {
        float x  = af[((size_t)b*TT + t)*DD + (DD-1)];
        float sg = 1.0f / (1.0f + expf(-x));
        if (t >= nf) sg = 0.f;
        sh[t] = sg;
        s += sg;
    }
    red[threadIdx.x] = s;
    __syncthreads();
    for (int o = 128; o > 0; o >>= 1) {
        if (threadIdx.x < o) red[threadIdx.x] += red[threadIdx.x + o];
        __syncthreads();
    }
    float total = red[0];
    float scale = (float)g_nt[b] / total;
    for (int t = threadIdx.x; t < TT; t += 256)
        g_alphas[b*TT + t] = sh[t] * scale;
    if (threadIdx.x == 0) g_numpred[b] = total;
}

// ---------------------------------------------------------------------------
// Kernel 2: exact CIF scan. One warp; lanes 0..15 = batches. Emits sorted
// (n, t, w) pairs per batch (token_index is monotone), then builds CSR
// row pointers. Faithfully replicates:
//   - alpha_needed = 1 - integrate BEFORE accumulation
//   - scatter .set() semantics (overwrite on same index within a frame)
//   - min(idx+1, nt-1) clamp
//   - the batched jnp.any() coupling of the 3 extra-fire passes
//   - the final frame's remainder being dropped
// ---------------------------------------------------------------------------
__global__ void k_cif() {
    int lane = threadIdx.x;
    const unsigned FULL = 0xFFFFu;
    if (lane >= BB) return;
    int b = lane;
    float integrate = 0.f, remainds = 0.f;
    int idx = 0;
    int nt1 = g_nt[b] - 1;
    int base = b * MAXP;
    int pcnt = 0;
    int   pn[6]; float pw[6]; int pc = 0;

    for (int t = 0; t < TT; t++) {
        if (t > 0) {
            // finalize frame t-1: scatter-ADD of remainder at current idx
            if (remainds != 0.f && pc < 6) { pn[pc] = idx; pw[pc] = remainds; pc++; }
            for (int i = 0; i < pc; i++)
                if (pw[i] != 0.f && pcnt < MAXP) {
                    g_pair_n[base+pcnt] = pn[i];
                    g_pair_t[base+pcnt] = t-1;
                    g_pair_w[base+pcnt] = pw[i];
                    pcnt++;
                }
            pc = 0;
        }
        float a = g_alphas[b*TT + t];
        float alpha_needed = 1.f - integrate;
        integrate += a;
        bool ready = (integrate >= 1.f);
        if (ready) integrate -= 1.f;
        float aint = ready ? alpha_needed : a;
        pn[0] = idx; pw[0] = aint; pc = 1;            // .set into fresh column
        remainds = a - aint;
        if (ready) idx = min(idx + 1, nt1);

        #pragma unroll
        for (int e = 0; e < 3; e++) {
            bool any = __any_sync(FULL, integrate >= 1.f);
            if (any) {
                bool r2 = (integrate >= 1.f);
                if (r2) integrate -= 1.f;
                float ai2 = r2 ? 1.f : remainds;      // alpha_needed = 1, alpha = remainds
                int j;
                for (j = 0; j < pc; j++) if (pn[j] == idx) { pw[j] = ai2; break; }
                if (j == pc && pc < 6) { pn[pc] = idx; pw[pc] = ai2; pc++; }
                remainds = remainds - ai2;
                if (r2) idx = min(idx + 1, nt1);
            }
        }
    }
    // final frame T-1: flush WITHOUT its remainder (reference drops it)
    for (int i = 0; i < pc; i++)
        if (pw[i] != 0.f && pcnt < MAXP) {
            g_pair_n[base+pcnt] = pn[i];
            g_pair_t[base+pcnt] = TT-1;
            g_pair_w[base+pcnt] = pw[i];
            pcnt++;
        }
    // CSR row pointers (pairs are sorted by n)
    int* rp = &g_rowptr[b*(NTOK+1)];
    int p = 0;
    rp[0] = 0;
    for (int n = 0; n < NTOK; n++) {
        while (p < pcnt && g_pair_n[base+p] == n) p++;
        rp[n+1] = p;
    }
}

// ---------------------------------------------------------------------------
// Kernel 3: h1[b,n,:] = sum_pairs w * hidden[b,t,:]   (sparse weighted sum)
// One block per (b,n) row; 256 threads cover 1023 dims.
// ---------------------------------------------------------------------------
__global__ void k_h1(const float* __restrict__ af) {
    int r = blockIdx.x;
    int b = r / NTOK, n = r % NTOK;
    int s = g_rowptr[b*(NTOK+1) + n];
    int e = g_rowptr[b*(NTOK+1) + n + 1];
    int d = threadIdx.x;
    float a0 = 0.f, a1 = 0.f, a2 = 0.f, a3 = 0.f;
    for (int p = s; p < e; p++) {
        int   t = g_pair_t[b*MAXP + p];
        float w = g_pair_w[b*MAXP + p];
        const float* row = af + ((size_t)b*TT + t)*DD;
        a0 += w * row[d];
        a1 += w * row[d + 256];
        a2 += w * row[d + 512];
        if (d + 768 < DH) a3 += w * row[d + 768];
    }
    float* o = g_h1 + (size_t)r*DH;
    o[d] = a0; o[d+256] = a1; o[d+512] = a2;
    if (d + 768 < DH) o[d+768] = a3;
}

// ---------------------------------------------------------------------------
// Kernel 4/6: fp32 NT SGEMM  C[m,n] = sum_k A[m,k]*B[n,k] + bias[n]
// 128x128 block tile, BK=8, 256 threads, 8x8 per thread.
// ---------------------------------------------------------------------------
__global__ void __launch_bounds__(256)
sgemm_nt(int M, int N, int K,
         const float* __restrict__ A, int lda,
         const float* __restrict__ Bm, int ldb,
         const float* __restrict__ bias,
         float* __restrict__ C, int ldc)
{
    const int BM = 128, BN = 128, BK = 8, TM = 8, TN = 8;
    __shared__ float As[BK][BM];
    __shared__ float Bs[BK][BN];
    int tid = threadIdx.x;
    int m0 = blockIdx.y * BM;
    int n0 = blockIdx.x * BN;
    int tr = (tid / (BN/TN)) * TM;   // 16 thread-rows
    int tc = (tid % (BN/TN)) * TN;   // 16 thread-cols
    float acc[TM][TN];
    #pragma unroll
    for (int i = 0; i < TM; i++)
        #pragma unroll
        for (int j = 0; j < TN; j++) acc[i][j] = 0.f;

    for (int k0 = 0; k0 < K; k0 += BK) {
        #pragma unroll
        for (int i = tid; i < BM*BK; i += 256) {
            int m = i / BK, kk = i % BK;
            int gm = m0 + m, gk = k0 + kk;
            As[kk][m] = (gm < M && gk < K) ? A[(size_t)gm*lda + gk] : 0.f;
        }
        #pragma unroll
        for (int i = tid; i < BN*BK; i += 256) {
            int n = i / BK, kk = i % BK;
            int gn = n0 + n, gk = k0 + kk;
            Bs[kk][n] = (gn < N && gk < K) ? Bm[(size_t)gn*ldb + gk] : 0.f;
        }
        __syncthreads();
        #pragma unroll
        for (int kk = 0; kk < BK; kk++) {
            float ar[TM], br[TN];
            #pragma unroll
            for (int i = 0; i < TM; i++) ar[i] = As[kk][tr + i];
            #pragma unroll
            for (int j = 0; j < TN; j++) br[j] = Bs[kk][tc + j];
            #pragma unroll
            for (int i = 0; i < TM; i++)
                #pragma unroll
                for (int j = 0; j < TN; j++)
                    acc[i][j] += ar[i] * br[j];
        }
        __syncthreads();
    }
    #pragma unroll
    for (int i = 0; i < TM; i++) {
        int gm = m0 + tr + i;
        if (gm >= M) continue;
        #pragma unroll
        for (int j = 0; j < TN; j++) {
            int gn = n0 + tc + j;
            C[(size_t)gm*ldc + gn] = acc[i][j] + bias[gn];
        }
    }
}

// ---------------------------------------------------------------------------
// Kernel 5: RMSNorm in-place on g_h2 rows (fp32, eps=1e-6), apply ln_w.
// ---------------------------------------------------------------------------
__global__ void k_rms(const float* __restrict__ lnw) {
    int r = blockIdx.x;
    float* h = g_h2 + (size_t)r*DD;
    int tid = threadIdx.x;
    float v0 = h[tid], v1 = h[tid+256], v2 = h[tid+512], v3 = h[tid+768];
    __shared__ float red[256];
    red[tid] = v0*v0 + v1*v1 + v2*v2 + v3*v3;
    __syncthreads();
    for (int o = 128; o > 0; o >>= 1) {
        if (tid < o) red[tid] += red[tid + o];
        __syncthreads();
    }
    float inv = rsqrtf(red[0] * (1.0f/DD) + 1e-6f);
    h[tid]     = v0 * inv * lnw[tid];
    h[tid+256] = v1 * inv * lnw[tid+256];
    h[tid+512] = v2 * inv * lnw[tid+512];
    h[tid+768] = v3 * inv * lnw[tid+768];
}

// ---------------------------------------------------------------------------
// Kernel 7: optional tail outputs (num_audio_tokens, num_pred_audio_tokens)
// if the harness buffer has room for them.
// ---------------------------------------------------------------------------
__global__ void k_tail(float* __restrict__ out, int out_size) {
    int i = threadIdx.x;
    if (i < BB && out_size >= MM*DTXT + 2*BB) {
        out[MM*DTXT + i]      = (float)g_nt[i];
        out[MM*DTXT + BB + i] = g_numpred[i];
    }
}

// ---------------------------------------------------------------------------
extern "C" void kernel_launch(void* const* d_in, const int* in_sizes, int n_in,
                              void* d_out, int out_size) {
    const float* af     = (const float*)d_in[0];
    const float* cif_w  = (const float*)d_in[1];
    const float* cif_b  = (const float*)d_in[2];
    const float* ln_w   = (const float*)d_in[3];
    const float* text_w = (const float*)d_in[4];
    const float* text_b = (const float*)d_in[5];
    const void*  nf     = d_in[6];
    const void*  nt     = d_in[7];
    float* out = (float*)d_out;

    void *p_h1 = nullptr, *p_h2 = nullptr;
    cudaGetSymbolAddress(&p_h1, g_h1);
    cudaGetSymbolAddress(&p_h2, g_h2);

    k_detect<<<1, 1>>>(nf, nt);
    k_alphas<<<BB, 256>>>(af);
    k_cif<<<1, 32>>>();
    k_h1<<<MM, 256>>>(af);

    // cif_proj: [6000,1023] x [1024,1023]^T -> g_h2 [6000,1024]
    {
        dim3 grid(DD/128, (MM + 127)/128);
        sgemm_nt<<<grid, 256>>>(MM, DD, DH,
                                (const float*)p_h1, DH,
                                cif_w, DH,
                                cif_b,
                                (float*)p_h2, DD);
    }
    k_rms<<<MM, 256>>>(ln_w);

    // text_proj: [6000,1024] x [4096,1024]^T -> out [6000,4096]
    {
        dim3 grid(DTXT/128, (MM + 127)/128);
        sgemm_nt<<<grid, 256>>>(MM, DTXT, DD,
                                (const float*)p_h2, DD,
                                text_w, DD,
                                text_b,
                                out, DTXT);
    }
    k_tail<<<1, 32>>>(out, out_size);
}

// round 2
// speedup vs baseline: 1.6019x; 1.6019x over previous
#include <cuda_runtime.h>
#include <math.h>
#include <stdint.h>

// ---------------------------------------------------------------------------
// Problem dimensions (fixed by the dataset)
// ---------------------------------------------------------------------------
#define BB   16
#define TT   1500
#define DD   1024
#define DH   1023          // D-1 hidden dim fed to CIF
#define DTXT 4096
#define NTOK 375
#define MM   (BB*NTOK)     // 6000 rows
#define MAXP 12288
#define LDH  1024          // padded leading dim for g_h1

// ---------------------------------------------------------------------------
// Device scratch
// ---------------------------------------------------------------------------
__device__ float g_alphas[BB*TT];
__device__ float g_numpred[BB];
__device__ int   g_nf[BB];
__device__ int   g_nt[BB];
__device__ int   g_pair_n[BB*MAXP];
__device__ int   g_pair_t[BB*MAXP];
__device__ float g_pair_w[BB*MAXP];
__device__ int   g_rowptr[BB*(NTOK+1)];
__device__ float g_h1[(size_t)MM*LDH];     // CIF output [B,N,1024] (col 1023 = 0)
__device__ float g_h2[(size_t)MM*DD];      // cif_proj out / rmsnorm in-place
__device__ float g_w1[(size_t)DD*DD];      // padded cif_w [1024,1024] (col 1023 = 0)

// ---------------------------------------------------------------------------
// Kernel 0: int64/int32 detection for num_frames / num_text_tokens
// ---------------------------------------------------------------------------
__global__ void k_detect(const void* nf_raw, const void* nt_raw) {
    const int* a = (const int*)nf_raw;
    const int* b = (const int*)nt_raw;
    bool is64 = (a[1] == 0);
    for (int i = 0; i < BB; i++) {
        if (is64) {
            g_nf[i] = (int)((const long long*)nf_raw)[i];
            g_nt[i] = (int)((const long long*)nt_raw)[i];
        } else {
            g_nf[i] = a[i];
            g_nt[i] = b[i];
        }
    }
}

// ---------------------------------------------------------------------------
// Kernel 1: masked sigmoid, per-batch sum, scale
// ---------------------------------------------------------------------------
__global__ void k_alphas(const float* __restrict__ af) {
    int b = blockIdx.x;
    __shared__ float sh[TT];
    __shared__ float red[256];
    int nf = g_nf[b];
    float s = 0.f;
    for (int t = threadIdx.x; t < TT; t += 256) {
        float x  = af[((size_t)b*TT + t)*DD + (DD-1)];
        float sg = 1.0f / (1.0f + expf(-x));
        if (t >= nf) sg = 0.f;
        sh[t] = sg;
        s += sg;
    }
    red[threadIdx.x] = s;
    __syncthreads();
    for (int o = 128; o > 0; o >>= 1) {
        if (threadIdx.x < o) red[threadIdx.x] += red[threadIdx.x + o];
        __syncthreads();
    }
    float total = red[0];
    float scale = (float)g_nt[b] / total;
    for (int t = threadIdx.x; t < TT; t += 256)
        g_alphas[b*TT + t] = sh[t] * scale;
    if (threadIdx.x == 0) g_numpred[b] = total;
}

// ---------------------------------------------------------------------------
// Kernel 2: exact CIF scan (unchanged from passing round-1 version)
// ---------------------------------------------------------------------------
__global__ void k_cif() {
    int lane = threadIdx.x;
    const unsigned FULL = 0xFFFFu;
    if (lane >= BB) return;
    int b = lane;
    float integrate = 0.f, remainds = 0.f;
    int idx = 0;
    int nt1 = g_nt[b] - 1;
    int base = b * MAXP;
    int pcnt = 0;
    int   pn[6]; float pw[6]; int pc = 0;

    for (int t = 0; t < TT; t++) {
        if (t > 0) {
            if (remainds != 0.f && pc < 6) { pn[pc] = idx; pw[pc] = remainds; pc++; }
            for (int i = 0; i < pc; i++)
                if (pw[i] != 0.f && pcnt < MAXP) {
                    g_pair_n[base+pcnt] = pn[i];
                    g_pair_t[base+pcnt] = t-1;
                    g_pair_w[base+pcnt] = pw[i];
                    pcnt++;
                }
            pc = 0;
        }
        float a = g_alphas[b*TT + t];
        float alpha_needed = 1.f - integrate;
        integrate += a;
        bool ready = (integrate >= 1.f);
        if (ready) integrate -= 1.f;
        float aint = ready ? alpha_needed : a;
        pn[0] = idx; pw[0] = aint; pc = 1;
        remainds = a - aint;
        if (ready) idx = min(idx + 1, nt1);

        #pragma unroll
        for (int e = 0; e < 3; e++) {
            bool any = __any_sync(FULL, integrate >= 1.f);
            if (any) {
                bool r2 = (integrate >= 1.f);
                if (r2) integrate -= 1.f;
                float ai2 = r2 ? 1.f : remainds;
                int j;
                for (j = 0; j < pc; j++) if (pn[j] == idx) { pw[j] = ai2; break; }
                if (j == pc && pc < 6) { pn[pc] = idx; pw[pc] = ai2; pc++; }
                remainds = remainds - ai2;
                if (r2) idx = min(idx + 1, nt1);
            }
        }
    }
    for (int i = 0; i < pc; i++)
        if (pw[i] != 0.f && pcnt < MAXP) {
            g_pair_n[base+pcnt] = pn[i];
            g_pair_t[base+pcnt] = TT-1;
            g_pair_w[base+pcnt] = pw[i];
            pcnt++;
        }
    int* rp = &g_rowptr[b*(NTOK+1)];
    int p = 0;
    rp[0] = 0;
    for (int n = 0; n < NTOK; n++) {
        while (p < pcnt && g_pair_n[base+p] == n) p++;
        rp[n+1] = p;
    }
}

// ---------------------------------------------------------------------------
// Kernel 3: h1[b,n,:] = sum_pairs w * hidden[b,t,:]  (ld=1024, pad col zeroed)
// ---------------------------------------------------------------------------
__global__ void k_h1(const float* __restrict__ af) {
    int r = blockIdx.x;
    int b = r / NTOK, n = r % NTOK;
    int s = g_rowptr[b*(NTOK+1) + n];
    int e = g_rowptr[b*(NTOK+1) + n + 1];
    int d = threadIdx.x;
    float a0 = 0.f, a1 = 0.f, a2 = 0.f, a3 = 0.f;
    for (int p = s; p < e; p++) {
        int   t = g_pair_t[b*MAXP + p];
        float w = g_pair_w[b*MAXP + p];
        const float* row = af + ((size_t)b*TT + t)*DD;
        a0 += w * row[d];
        a1 += w * row[d + 256];
        a2 += w * row[d + 512];
        if (d + 768 < DH) a3 += w * row[d + 768];
    }
    float* o = g_h1 + (size_t)r*LDH;
    o[d] = a0; o[d+256] = a1; o[d+512] = a2;
    if (d + 768 < DH) o[d+768] = a3;
    else              o[1023]  = 0.f;   // zero pad column (thread 255)
}

// ---------------------------------------------------------------------------
// Kernel 3b: pad cif_w [1024,1023] -> g_w1 [1024,1024] (col 1023 = 0)
// ---------------------------------------------------------------------------
__global__ void k_padw(const float* __restrict__ w) {
    int i = blockIdx.x * 256 + threadIdx.x;     // grid covers 1024*1024
    int n = i >> 10, k = i & 1023;
    g_w1[i] = (k < DH) ? w[(size_t)n*DH + k] : 0.f;
}

// ---------------------------------------------------------------------------
// TF32 tensor-core GEMM, 3xTF32 split.  C[m,n] = sum_k A[m,k]*B[n,k] + bias[n]
// 128x128 CTA tile, BK=16, 256 threads, warp tile 64x32 (4x4 m16n8k8).
// Requires lda, ldb multiples of 4 (16B-aligned rows) for cp.async.
// ---------------------------------------------------------------------------
#define SA 20   // smem row stride in floats (conflict-free for tf32 fragments)

__device__ __forceinline__ uint32_t f2tf(float x) {
    uint32_t r; asm("cvt.rna.tf32.f32 %0, %1;" : "=r"(r) : "f"(x)); return r;
}
__device__ __forceinline__ void split_tf32(float x, uint32_t& hi, uint32_t& lo) {
    hi = f2tf(x);
    lo = f2tf(x - __uint_as_float(hi));
}
__device__ __forceinline__ void mma_tf32(float d[4], const uint32_t a[4], const uint32_t b[2]) {
    asm volatile(
        "mma.sync.aligned.m16n8k8.row.col.f32.tf32.tf32.f32 "
        "{%0,%1,%2,%3}, {%4,%5,%6,%7}, {%8,%9}, {%0,%1,%2,%3};"
        : "+f"(d[0]), "+f"(d[1]), "+f"(d[2]), "+f"(d[3])
        : "r"(a[0]), "r"(a[1]), "r"(a[2]), "r"(a[3]), "r"(b[0]), "r"(b[1]));
}
__device__ __forceinline__ void cp16(uint32_t dst, const float* src, int bytes) {
    asm volatile("cp.async.ca.shared.global [%0], [%1], 16, %2;"
                 :: "r"(dst), "l"(src), "r"(bytes));
}

__global__ void __launch_bounds__(256)
gemm_tf32(int M, int N, int K,
          const float* __restrict__ A, int lda,
          const float* __restrict__ B, int ldb,
          const float* __restrict__ bias,
          float* __restrict__ C, int ldc)
{
    __shared__ __align__(16) float As[2][128*SA];
    __shared__ __align__(16) float Bs[2][128*SA];
    int tid  = threadIdx.x;
    int m0   = blockIdx.y * 128;
    int n0   = blockIdx.x * 128;
    int wid  = tid >> 5, lane = tid & 31;
    int gid  = lane >> 2, tig = lane & 3;
    int wm   = (wid & 1) * 64;     // warp m-offset
    int wn   = (wid >> 1) * 32;    // warp n-offset

    float acc[4][4][4];
    #pragma unroll
    for (int i = 0; i < 4; i++)
        #pragma unroll
        for (int j = 0; j < 4; j++)
            #pragma unroll
            for (int q = 0; q < 4; q++) acc[i][j][q] = 0.f;

    int ntiles = (K + 15) >> 4;

    uint32_t sA = (uint32_t)__cvta_generic_to_shared(&As[0][0]);
    uint32_t sB = (uint32_t)__cvta_generic_to_shared(&Bs[0][0]);
    const uint32_t BUFB = 128*SA*4;   // bytes per buffer

    // ---- tile loader (A and B tiles, 512 16B chunks each) ----
    auto load_tile = [&](int kt, int buf) {
        int k0 = kt << 4;
        #pragma unroll
        for (int c = tid; c < 512; c += 256) {
            int m = c >> 2, ch = (c & 3) << 2;
            int gm = m0 + m, gk = k0 + ch;
            int bytes = 0;
            const float* src = A;
            if (gm < M) {
                int rem = K - gk;
                bytes = rem >= 4 ? 16 : (rem > 0 ? rem*4 : 0);
                src = A + (size_t)gm*lda + gk;
            }
            cp16(sA + buf*BUFB + (m*SA + ch)*4, src, bytes);
        }
        #pragma unroll
        for (int c = tid; c < 512; c += 256) {
            int n = c >> 2, ch = (c & 3) << 2;
            int gn = n0 + n, gk = k0 + ch;
            int bytes = 0;
            const float* src = B;
            if (gn < N) {
                int rem = K - gk;
                bytes = rem >= 4 ? 16 : (rem > 0 ? rem*4 : 0);
                src = B + (size_t)gn*ldb + gk;
            }
            cp16(sB + buf*BUFB + (n*SA + ch)*4, src, bytes);
        }
        asm volatile("cp.async.commit_group;");
    };

    load_tile(0, 0);

    for (int kt = 0; kt < ntiles; kt++) {
        int buf = kt & 1;
        if (kt + 1 < ntiles) {
            load_tile(kt + 1, buf ^ 1);
            asm volatile("cp.async.wait_group 1;");
        } else {
            asm volatile("cp.async.wait_group 0;");
        }
        __syncthreads();

        const float* ap = &As[buf][0];
        const float* bp = &Bs[buf][0];

        #pragma unroll
        for (int ks = 0; ks < 2; ks++) {
            int kc = ks*8 + tig;
            uint32_t ah[4][4], al[4][4], bh[4][2], bl[4][2];
            #pragma unroll
            for (int mi = 0; mi < 4; mi++) {
                int r = wm + mi*16 + gid;
                split_tf32(ap[ r     *SA + kc    ], ah[mi][0], al[mi][0]);
                split_tf32(ap[(r + 8)*SA + kc    ], ah[mi][1], al[mi][1]);
                split_tf32(ap[ r     *SA + kc + 4], ah[mi][2], al[mi][2]);
                split_tf32(ap[(r + 8)*SA + kc + 4], ah[mi][3], al[mi][3]);
            }
            #pragma unroll
            for (int ni = 0; ni < 4; ni++) {
                int nr = wn + ni*8 + gid;
                split_tf32(bp[nr*SA + kc    ], bh[ni][0], bl[ni][0]);
                split_tf32(bp[nr*SA + kc + 4], bh[ni][1], bl[ni][1]);
            }
            #pragma unroll
            for (int mi = 0; mi < 4; mi++)
                #pragma unroll
                for (int ni = 0; ni < 4; ni++) {
                    mma_tf32(acc[mi][ni], al[mi], bh[ni]);   // lo*hi
                    mma_tf32(acc[mi][ni], ah[mi], bl[ni]);   // hi*lo
                    mma_tf32(acc[mi][ni], ah[mi], bh[ni]);   // hi*hi
                }
        }
        __syncthreads();
    }

    // ---- epilogue ----
    #pragma unroll
    for (int mi = 0; mi < 4; mi++) {
        int row = m0 + wm + mi*16 + gid;
        #pragma unroll
        for (int ni = 0; ni < 4; ni++) {
            int col = n0 + wn + ni*8 + 2*tig;
            float b0 = bias[col], b1 = bias[col+1];
            if (row < M) {
                C[(size_t)row*ldc + col    ] = acc[mi][ni][0] + b0;
                C[(size_t)row*ldc + col + 1] = acc[mi][ni][1] + b1;
            }
            if (row + 8 < M) {
                C[(size_t)(row+8)*ldc + col    ] = acc[mi][ni][2] + b0;
                C[(size_t)(row+8)*ldc + col + 1] = acc[mi][ni][3] + b1;
            }
        }
    }
}

// ---------------------------------------------------------------------------
// Kernel 5: RMSNorm in-place on g_h2 rows
// ---------------------------------------------------------------------------
__global__ void k_rms(const float* __restrict__ lnw) {
    int r = blockIdx.x;
    float* h = g_h2 + (size_t)r*DD;
    int tid = threadIdx.x;
    float v0 = h[tid], v1 = h[tid+256], v2 = h[tid+512], v3 = h[tid+768];
    __shared__ float red[256];
    red[tid] = v0*v0 + v1*v1 + v2*v2 + v3*v3;
    __syncthreads();
    for (int o = 128; o > 0; o >>= 1) {
        if (tid < o) red[tid] += red[tid + o];
        __syncthreads();
    }
    float inv = rsqrtf(red[0] * (1.0f/DD) + 1e-6f);
    h[tid]     = v0 * inv * lnw[tid];
    h[tid+256] = v1 * inv * lnw[tid+256];
    h[tid+512] = v2 * inv * lnw[tid+512];
    h[tid+768] = v3 * inv * lnw[tid+768];
}

// ---------------------------------------------------------------------------
// Kernel 7: optional tail outputs
// ---------------------------------------------------------------------------
__global__ void k_tail(float* __restrict__ out, int out_size) {
    int i = threadIdx.x;
    if (i < BB && out_size >= MM*DTXT + 2*BB) {
        out[MM*DTXT + i]      = (float)g_nt[i];
        out[MM*DTXT + BB + i] = g_numpred[i];
    }
}

// ---------------------------------------------------------------------------
extern "C" void kernel_launch(void* const* d_in, const int* in_sizes, int n_in,
                              void* d_out, int out_size) {
    const float* af     = (const float*)d_in[0];
    const float* cif_w  = (const float*)d_in[1];
    const float* cif_b  = (const float*)d_in[2];
    const float* ln_w   = (const float*)d_in[3];
    const float* text_w = (const float*)d_in[4];
    const float* text_b = (const float*)d_in[5];
    const void*  nf     = d_in[6];
    const void*  nt     = d_in[7];
    float* out = (float*)d_out;

    void *p_h1 = nullptr, *p_h2 = nullptr, *p_w1 = nullptr;
    cudaGetSymbolAddress(&p_h1, g_h1);
    cudaGetSymbolAddress(&p_h2, g_h2);
    cudaGetSymbolAddress(&p_w1, g_w1);

    k_detect<<<1, 1>>>(nf, nt);
    k_alphas<<<BB, 256>>>(af);
    k_cif<<<1, 32>>>();
    k_h1<<<MM, 256>>>(af);
    k_padw<<<(DD*DD)/256, 256>>>(cif_w);

    // cif_proj: [6000,1024(pad)] x [1024,1024(pad)]^T -> g_h2 [6000,1024]
    {
        dim3 grid(DD/128, (MM + 127)/128);
        gemm_tf32<<<grid, 256>>>(MM, DD, 1024,
                                 (const float*)p_h1, LDH,
                                 (const float*)p_w1, 1024,
                                 cif_b,
                                 (float*)p_h2, DD);
    }
    k_rms<<<MM, 256>>>(ln_w);

    // text_proj: [6000,1024] x [4096,1024]^T -> out [6000,4096]
    {
        dim3 grid(DTXT/128, (MM + 127)/128);
        gemm_tf32<<<grid, 256>>>(MM, DTXT, DD,
                                 (const float*)p_h2, DD,
                                 text_w, DD,
                                 text_b,
                                 out, DTXT);
    }
    k_tail<<<1, 32>>>(out, out_size);
}

// round 5
// speedup vs baseline: 2.2320x; 1.3934x over previous
#include <cuda_runtime.h>
#include <cuda_bf16.h>
#include <math.h>
#include <stdint.h>

// ---------------------------------------------------------------------------
// Problem dimensions (fixed by the dataset)
// ---------------------------------------------------------------------------
#define BB   16
#define TT   1500
#define DD   1024
#define DH   1023
#define DTXT 4096
#define NTOK 375
#define MM   (BB*NTOK)     // 6000
#define MAXP 12288
#define LDH  1024

// ---------------------------------------------------------------------------
// Device scratch
// ---------------------------------------------------------------------------
__device__ float g_alphas[BB*TT];
__device__ float g_numpred[BB];
__device__ int   g_nf[BB];
__device__ int   g_nt[BB];
__device__ int   g_pair_n[BB*MAXP];
__device__ int   g_pair_t[BB*MAXP];
__device__ float g_pair_w[BB*MAXP];
__device__ int   g_rowptr[BB*(NTOK+1)];
__device__ float g_h2 [(size_t)MM*DD];            // cif_proj out
__device__ __nv_bfloat16 g_ahi[(size_t)MM*LDH];   // A hi split
__device__ __nv_bfloat16 g_alo[(size_t)MM*LDH];   // A lo split
__device__ __nv_bfloat16 g_bhi[(size_t)DTXT*DD];  // B hi split
__device__ __nv_bfloat16 g_blo[(size_t)DTXT*DD];  // B lo split

// ---------------------------------------------------------------------------
// bf16 split: x = hi + lo + O(2^-18 x)
// ---------------------------------------------------------------------------
__device__ __forceinline__ void split_bf(float x, __nv_bfloat16& h, __nv_bfloat16& l) {
    h = __float2bfloat16(x);
    l = __float2bfloat16(x - __bfloat162float(h));
}

// ---------------------------------------------------------------------------
// Kernel 0: int64/int32 detection
// ---------------------------------------------------------------------------
__global__ void k_detect(const void* nf_raw, const void* nt_raw) {
    const int* a = (const int*)nf_raw;
    const int* b = (const int*)nt_raw;
    bool is64 = (a[1] == 0) && (a[3] == 0) && (a[5] == 0);
    for (int i = 0; i < BB; i++) {
        if (is64) {
            g_nf[i] = (int)((const long long*)nf_raw)[i];
            g_nt[i] = (int)((const long long*)nt_raw)[i];
        } else {
            g_nf[i] = a[i];
            g_nt[i] = b[i];
        }
    }
}

// ---------------------------------------------------------------------------
// Kernel 1: masked sigmoid, per-batch sum, scale
// ---------------------------------------------------------------------------
__global__ void k_alphas(const float* __restrict__ af) {
    int b = blockIdx.x;
    __shared__ float sh[TT];
    __shared__ float red[256];
    int nf = g_nf[b];
    float s = 0.f;
    for (int t = threadIdx.x; t < TT; t += 256) {
        float x  = af[((size_t)b*TT + t)*DD + (DD-1)];
        float sg = 1.0f / (1.0f + expf(-x));
        if (t >= nf) sg = 0.f;
        sh[t] = sg;
        s += sg;
    }
    red[threadIdx.x] = s;
    __syncthreads();
    for (int o = 128; o > 0; o >>= 1) {
        if (threadIdx.x < o) red[threadIdx.x] += red[threadIdx.x + o];
        __syncthreads();
    }
    float total = red[0];
    float scale = (float)g_nt[b] / total;
    for (int t = threadIdx.x; t < TT; t += 256)
        g_alphas[b*TT + t] = sh[t] * scale;
    if (threadIdx.x == 0) g_numpred[b] = total;
}

// ---------------------------------------------------------------------------
// Kernel 2: exact CIF scan (verified correct in R1/R2)
// ---------------------------------------------------------------------------
__global__ void k_cif() {
    int lane = threadIdx.x;
    const unsigned FULL = 0xFFFFu;
    if (lane >= BB) return;
    int b = lane;
    float integrate = 0.f, remainds = 0.f;
    int idx = 0;
    int nt1 = g_nt[b] - 1;
    int base = b * MAXP;
    int pcnt = 0;
    int   pn[6]; float pw[6]; int pc = 0;

    for (int t = 0; t < TT; t++) {
        if (t > 0) {
            if (remainds != 0.f && pc < 6) { pn[pc] = idx; pw[pc] = remainds; pc++; }
            for (int i = 0; i < pc; i++)
                if (pw[i] != 0.f && pcnt < MAXP) {
                    g_pair_n[base+pcnt] = pn[i];
                    g_pair_t[base+pcnt] = t-1;
                    g_pair_w[base+pcnt] = pw[i];
                    pcnt++;
                }
            pc = 0;
        }
        float a = g_alphas[b*TT + t];
        float alpha_needed = 1.f - integrate;
        integrate += a;
        bool ready = (integrate >= 1.f);
        if (ready) integrate -= 1.f;
        float aint = ready ? alpha_needed : a;
        pn[0] = idx; pw[0] = aint; pc = 1;
        remainds = a - aint;
        if (ready) idx = min(idx + 1, nt1);

        #pragma unroll
        for (int e = 0; e < 3; e++) {
            bool any = __any_sync(FULL, integrate >= 1.f);
            if (any) {
                bool r2 = (integrate >= 1.f);
                if (r2) integrate -= 1.f;
                float ai2 = r2 ? 1.f : remainds;
                int j;
                for (j = 0; j < pc; j++) if (pn[j] == idx) { pw[j] = ai2; break; }
                if (j == pc && pc < 6) { pn[pc] = idx; pw[pc] = ai2; pc++; }
                remainds = remainds - ai2;
                if (r2) idx = min(idx + 1, nt1);
            }
        }
    }
    for (int i = 0; i < pc; i++)
        if (pw[i] != 0.f && pcnt < MAXP) {
            g_pair_n[base+pcnt] = pn[i];
            g_pair_t[base+pcnt] = TT-1;
            g_pair_w[base+pcnt] = pw[i];
            pcnt++;
        }
    int* rp = &g_rowptr[b*(NTOK+1)];
    int p = 0;
    rp[0] = 0;
    for (int n = 0; n < NTOK; n++) {
        while (p < pcnt && g_pair_n[base+p] == n) p++;
        rp[n+1] = p;
    }
}

// ---------------------------------------------------------------------------
// Kernel 3: h1 = CIF sparse sum, written as bf16 hi/lo splits
// ---------------------------------------------------------------------------
__global__ void k_h1(const float* __restrict__ af) {
    int r = blockIdx.x;
    int b = r / NTOK, n = r % NTOK;
    int s = g_rowptr[b*(NTOK+1) + n];
    int e = g_rowptr[b*(NTOK+1) + n + 1];
    int d = threadIdx.x;
    float a0 = 0.f, a1 = 0.f, a2 = 0.f, a3 = 0.f;
    for (int p = s; p < e; p++) {
        int   t = g_pair_t[b*MAXP + p];
        float w = g_pair_w[b*MAXP + p];
        const float* row = af + ((size_t)b*TT + t)*DD;
        a0 += w * row[d];
        a1 += w * row[d + 256];
        a2 += w * row[d + 512];
        if (d + 768 < DH) a3 += w * row[d + 768];
    }
    size_t o = (size_t)r*LDH;
    __nv_bfloat16 h, l;
    split_bf(a0, h, l); g_ahi[o+d]     = h; g_alo[o+d]     = l;
    split_bf(a1, h, l); g_ahi[o+d+256] = h; g_alo[o+d+256] = l;
    split_bf(a2, h, l); g_ahi[o+d+512] = h; g_alo[o+d+512] = l;
    if (d + 768 < DH) { split_bf(a3, h, l); g_ahi[o+d+768] = h; g_alo[o+d+768] = l; }
    else { g_ahi[o+1023] = __float2bfloat16(0.f); g_alo[o+1023] = __float2bfloat16(0.f); }
}

// ---------------------------------------------------------------------------
// Kernel 3b: pad+split cif_w [1024,1023] -> bf16 hi/lo [1024,1024]
// ---------------------------------------------------------------------------
__global__ void k_padw_split(const float* __restrict__ w) {
    int i = blockIdx.x * 256 + threadIdx.x;
    int n = i >> 10, k = i & 1023;
    float v = (k < DH) ? w[(size_t)n*DH + k] : 0.f;
    __nv_bfloat16 h, l; split_bf(v, h, l);
    g_bhi[i] = h; g_blo[i] = l;
}

// ---------------------------------------------------------------------------
// Kernel 3c: split text_w [4096,1024] -> bf16 hi/lo
// ---------------------------------------------------------------------------
__global__ void k_split_w(const float* __restrict__ w) {
    int i = blockIdx.x * 256 + threadIdx.x;
    __nv_bfloat16 h, l; split_bf(w[i], h, l);
    g_bhi[i] = h; g_blo[i] = l;
}

// ---------------------------------------------------------------------------
// Kernel 5: RMSNorm on g_h2, write normalized rows as bf16 hi/lo splits
// ---------------------------------------------------------------------------
__global__ void k_rms(const float* __restrict__ lnw) {
    int r = blockIdx.x;
    const float* hp = g_h2 + (size_t)r*DD;
    int tid = threadIdx.x;
    float v0 = hp[tid], v1 = hp[tid+256], v2 = hp[tid+512], v3 = hp[tid+768];
    __shared__ float red[256];
    red[tid] = v0*v0 + v1*v1 + v2*v2 + v3*v3;
    __syncthreads();
    for (int o = 128; o > 0; o >>= 1) {
        if (tid < o) red[tid] += red[tid + o];
        __syncthreads();
    }
    float inv = rsqrtf(red[0] * (1.0f/DD) + 1e-6f);
    size_t o = (size_t)r*DD;
    __nv_bfloat16 h, l;
    split_bf(v0*inv*lnw[tid],     h, l); g_ahi[o+tid]     = h; g_alo[o+tid]     = l;
    split_bf(v1*inv*lnw[tid+256], h, l); g_ahi[o+tid+256] = h; g_alo[o+tid+256] = l;
    split_bf(v2*inv*lnw[tid+512], h, l); g_ahi[o+tid+512] = h; g_alo[o+tid+512] = l;
    split_bf(v3*inv*lnw[tid+768], h, l); g_ahi[o+tid+768] = h; g_alo[o+tid+768] = l;
}

// ---------------------------------------------------------------------------
// bf16 3-pass tensor-core GEMM (mma.sync.m16n8k16, pre-split operands).
// C[m,n] = sum_k (Ah+Al)[m,k]*(Bh+Bl)[n,k] + bias[n]  (ll term dropped)
// 128x128 CTA tile, BK=32, 256 threads, warp tile 64x32.
// ---------------------------------------------------------------------------
#define ASTRIDE   40                       // smem row stride in bf16 (80 B)
#define TILE_BYTES (128*ASTRIDE*2)         // 10240 B per operand-part tile
#define STAGEB    (4*TILE_BYTES)           // Ah,Al,Bh,Bl = 40960 B
#define GSMEM     (2*STAGEB)               // 81920 B double-buffered

__device__ __forceinline__ void cp16(uint32_t dst, const void* src) {
    asm volatile("cp.async.cg.shared.global [%0], [%1], 16;"
                 :: "r"(dst), "l"(src) : "memory");
}
__device__ __forceinline__ void ldsm4(uint32_t r[4], uint32_t addr) {
    asm volatile("ldmatrix.sync.aligned.m8n8.x4.shared.b16 {%0,%1,%2,%3}, [%4];"
                 : "=r"(r[0]), "=r"(r[1]), "=r"(r[2]), "=r"(r[3]) : "r"(addr));
}
__device__ __forceinline__ void mma_bf(float d[4], const uint32_t a[4],
                                       uint32_t b0, uint32_t b1) {
    asm volatile(
        "mma.sync.aligned.m16n8k16.row.col.f32.bf16.bf16.f32 "
        "{%0,%1,%2,%3}, {%4,%5,%6,%7}, {%8,%9}, {%0,%1,%2,%3};"
        : "+f"(d[0]), "+f"(d[1]), "+f"(d[2]), "+f"(d[3])
        : "r"(a[0]), "r"(a[1]), "r"(a[2]), "r"(a[3]), "r"(b0), "r"(b1));
}

__global__ void __launch_bounds__(256)
gemm_bf3(int M, int K,
         const __nv_bfloat16* __restrict__ Ah, const __nv_bfloat16* __restrict__ Al, int lda,
         const __nv_bfloat16* __restrict__ Bh, const __nv_bfloat16* __restrict__ Bl, int ldb,
         const float* __restrict__ bias,
         float* __restrict__ C, int ldc)
{
    extern __shared__ __align__(128) char smem[];
    uint32_t sbase = (uint32_t)__cvta_generic_to_shared(smem);

    int tid  = threadIdx.x;
    int wid  = tid >> 5, lane = tid & 31;
    int g    = lane >> 2, tig = lane & 3;
    int m0   = blockIdx.y * 128;
    int n0   = blockIdx.x * 128;
    int wm   = (wid & 1) * 64;
    int wn   = (wid >> 1) * 32;

    float acc[4][4][4];
    #pragma unroll
    for (int i = 0; i < 4; i++)
        #pragma unroll
        for (int j = 0; j < 4; j++)
            #pragma unroll
            for (int q = 0; q < 4; q++) acc[i][j][q] = 0.f;

    const int nt = K >> 5;   // K / 32

    // stage layout: [Ah | Al | Bh | Bl], each 128 rows x 80B
    auto load_stage = [&](int s, int kt) {
        uint32_t st = sbase + (uint32_t)s * STAGEB;
        int k0 = kt << 5;
        #pragma unroll
        for (int c = tid; c < 512; c += 256) {
            int row = c >> 2, ch = (c & 3) << 4;       // ch in bytes (0,16,32,48)
            int ke = k0 + (ch >> 1);                   // bf16 elem offset
            int gm = m0 + row; if (gm >= M) gm = M - 1;
            uint32_t d = st + row*80 + ch;
            cp16(d,                Ah + (size_t)gm*lda + ke);
            cp16(d + TILE_BYTES,   Al + (size_t)gm*lda + ke);
            size_t gb = (size_t)(n0 + row)*ldb + ke;   // N multiple of 128
            cp16(d + 2*TILE_BYTES, Bh + gb);
            cp16(d + 3*TILE_BYTES, Bl + gb);
        }
        asm volatile("cp.async.commit_group;" ::: "memory");
    };

    load_stage(0, 0);

    int quad = lane >> 3, qr = lane & 7;
    for (int kt = 0; kt < nt; kt++) {
        int buf = kt & 1;
        if (kt + 1 < nt) {
            load_stage(buf ^ 1, kt + 1);
            asm volatile("cp.async.wait_group 1;" ::: "memory");
        } else {
            asm volatile("cp.async.wait_group 0;" ::: "memory");
        }
        __syncthreads();

        uint32_t st = sbase + (uint32_t)buf * STAGEB;
        #pragma unroll
        for (int ks = 0; ks < 2; ks++) {
            int kc = ks * 16;
            // ldmatrix source addr for this lane (quad-mapped 16x16 load)
            uint32_t ka = (uint32_t)((kc + ((quad >> 1) << 3)) << 1);  // bytes
            uint32_t arow = st + (uint32_t)(wm + ((quad & 1) << 3) + qr) * 80 + ka;
            uint32_t brow = st + 2*TILE_BYTES
                          + (uint32_t)(wn + ((quad & 1) << 3) + qr) * 80 + ka;

            uint32_t ah[4][4], al[4][4], bh[2][4], bl[2][4];
            #pragma unroll
            for (int mi = 0; mi < 4; mi++) {
                ldsm4(ah[mi], arow + mi*16*80);
                ldsm4(al[mi], arow + TILE_BYTES + mi*16*80);
            }
            #pragma unroll
            for (int nb = 0; nb < 2; nb++) {
                ldsm4(bh[nb], brow + nb*16*80);
                ldsm4(bl[nb], brow + TILE_BYTES + nb*16*80);
            }
            #pragma unroll
            for (int mi = 0; mi < 4; mi++)
                #pragma unroll
                for (int ni = 0; ni < 4; ni++) {
                    int nb = ni >> 1, sel = ni & 1;
                    mma_bf(acc[mi][ni], ah[mi], bh[nb][sel], bh[nb][sel+2]); // hh
                    mma_bf(acc[mi][ni], ah[mi], bl[nb][sel], bl[nb][sel+2]); // hl
                    mma_bf(acc[mi][ni], al[mi], bh[nb][sel], bh[nb][sel+2]); // lh
                }
        }
        __syncthreads();
    }

    // ---- epilogue ----
    #pragma unroll
    for (int mi = 0; mi < 4; mi++) {
        int row0 = m0 + wm + mi*16 + g;
        int row1 = row0 + 8;
        #pragma unroll
        for (int ni = 0; ni < 4; ni++) {
            int col = n0 + wn + ni*8 + 2*tig;
            float b0 = bias[col], b1 = bias[col+1];
            if (row0 < M) {
                float2 v = { acc[mi][ni][0] + b0, acc[mi][ni][1] + b1 };
                *reinterpret_cast<float2*>(C + (size_t)row0*ldc + col) = v;
            }
            if (row1 < M) {
                float2 v = { acc[mi][ni][2] + b0, acc[mi][ni][3] + b1 };
                *reinterpret_cast<float2*>(C + (size_t)row1*ldc + col) = v;
            }
        }
    }
}

// ---------------------------------------------------------------------------
// Kernel 7: optional tail outputs
// ---------------------------------------------------------------------------
__global__ void k_tail(float* __restrict__ out, int out_size) {
    int i = threadIdx.x;
    if (i < BB && out_size >= MM*DTXT + 2*BB) {
        out[MM*DTXT + i]      = (float)g_nt[i];
        out[MM*DTXT + BB + i] = g_numpred[i];
    }
}

// ---------------------------------------------------------------------------
extern "C" void kernel_launch(void* const* d_in, const int* in_sizes, int n_in,
                              void* d_out, int out_size) {
    const float* af     = (const float*)d_in[0];
    const float* cif_w  = (const float*)d_in[1];
    const float* cif_b  = (const float*)d_in[2];
    const float* ln_w   = (const float*)d_in[3];
    const float* text_w = (const float*)d_in[4];
    const float* text_b = (const float*)d_in[5];
    const void*  nf     = d_in[6];
    const void*  nt     = d_in[7];
    float* out = (float*)d_out;

    void *p_h2=0, *p_ahi=0, *p_alo=0, *p_bhi=0, *p_blo=0;
    cudaGetSymbolAddress(&p_h2,  g_h2);
    cudaGetSymbolAddress(&p_ahi, g_ahi);
    cudaGetSymbolAddress(&p_alo, g_alo);
    cudaGetSymbolAddress(&p_bhi, g_bhi);
    cudaGetSymbolAddress(&p_blo, g_blo);

    cudaFuncSetAttribute(gemm_bf3, cudaFuncAttributeMaxDynamicSharedMemorySize, GSMEM);

    k_detect<<<1, 1>>>(nf, nt);
    k_alphas<<<BB, 256>>>(af);
    k_cif<<<1, 32>>>();
    k_h1<<<MM, 256>>>(af);                          // -> g_ahi/g_alo (bf16)
    k_padw_split<<<(DD*DD)/256, 256>>>(cif_w);      // -> g_bhi/g_blo (bf16)

    // cif_proj: [6000,1024] x [1024,1024]^T -> g_h2
    {
        dim3 grid(DD/128, (MM + 127)/128);
        gemm_bf3<<<grid, 256, GSMEM>>>(MM, 1024,
            (const __nv_bfloat16*)p_ahi, (const __nv_bfloat16*)p_alo, LDH,
            (const __nv_bfloat16*)p_bhi, (const __nv_bfloat16*)p_blo, 1024,
            cif_b, (float*)p_h2, DD);
    }
    k_rms<<<MM, 256>>>(ln_w);                       // g_h2 -> g_ahi/g_alo (normalized)
    k_split_w<<<(DTXT*DD)/256, 256>>>(text_w);      // -> g_bhi/g_blo

    // text_proj: [6000,1024] x [4096,1024]^T -> out
    {
        dim3 grid(DTXT/128, (MM + 127)/128);
        gemm_bf3<<<grid, 256, GSMEM>>>(MM, 1024,
            (const __nv_bfloat16*)p_ahi, (const __nv_bfloat16*)p_alo, DD,
            (const __nv_bfloat16*)p_bhi, (const __nv_bfloat16*)p_blo, DD,
            text_b, out, DTXT);
    }
    k_tail<<<1, 32>>>(out, out_size);
}

// round 6
// speedup vs baseline: 2.4259x; 1.0869x over previous
#include <cuda_runtime.h>
#include <cuda_fp16.h>
#include <math.h>
#include <stdint.h>

// ---------------------------------------------------------------------------
// Problem dimensions (fixed by the dataset)
// ---------------------------------------------------------------------------
#define BB   16
#define TT   1500
#define DD   1024
#define DH   1023
#define DTXT 4096
#define NTOK 375
#define MM   (BB*NTOK)     // 6000
#define MAXP 12288
#define LDH  1024

// ---------------------------------------------------------------------------
// Device scratch
// ---------------------------------------------------------------------------
__device__ float g_alphas[BB*TT];
__device__ float g_numpred[BB];
__device__ int   g_nf[BB];
__device__ int   g_nt[BB];
__device__ int   g_pair_n[BB*MAXP];
__device__ int   g_pair_t[BB*MAXP];
__device__ float g_pair_w[BB*MAXP];
__device__ int   g_rowptr[BB*(NTOK+1)];
__device__ float g_h2 [(size_t)MM*DD];          // cif_proj out
__device__ __half g_ahi[(size_t)MM*LDH];        // A hi split
__device__ __half g_alo[(size_t)MM*LDH];        // A lo split
__device__ __half g_bhi[(size_t)DTXT*DD];       // B hi split
__device__ __half g_blo[(size_t)DTXT*DD];       // B lo split (cif_w only)

// ---------------------------------------------------------------------------
// fp16 split: x = hi + lo + O(2^-22 x)
// ---------------------------------------------------------------------------
__device__ __forceinline__ void split_h(float x, __half& h, __half& l) {
    h = __float2half(x);
    l = __float2half(x - __half2float(h));
}

// ---------------------------------------------------------------------------
// Kernel 0: int64/int32 detection
// ---------------------------------------------------------------------------
__global__ void k_detect(const void* nf_raw, const void* nt_raw) {
    const int* a = (const int*)nf_raw;
    const int* b = (const int*)nt_raw;
    bool is64 = (a[1] == 0) && (a[3] == 0) && (a[5] == 0);
    for (int i = 0; i < BB; i++) {
        if (is64) {
            g_nf[i] = (int)((const long long*)nf_raw)[i];
            g_nt[i] = (int)((const long long*)nt_raw)[i];
        } else {
            g_nf[i] = a[i];
            g_nt[i] = b[i];
        }
    }
}

// ---------------------------------------------------------------------------
// Kernel 1: masked sigmoid, per-batch sum, scale
// ---------------------------------------------------------------------------
__global__ void k_alphas(const float* __restrict__ af) {
    int b = blockIdx.x;
    __shared__ float sh[TT];
    __shared__ float red[256];
    int nf = g_nf[b];
    float s = 0.f;
    for (int t = threadIdx.x; t < TT; t += 256) {
        float x  = af[((size_t)b*TT + t)*DD + (DD-1)];
        float sg = 1.0f / (1.0f + expf(-x));
        if (t >= nf) sg = 0.f;
        sh[t] = sg;
        s += sg;
    }
    red[threadIdx.x] = s;
    __syncthreads();
    for (int o = 128; o > 0; o >>= 1) {
        if (threadIdx.x < o) red[threadIdx.x] += red[threadIdx.x + o];
        __syncthreads();
    }
    float total = red[0];
    float scale = (float)g_nt[b] / total;
    for (int t = threadIdx.x; t < TT; t += 256)
        g_alphas[b*TT + t] = sh[t] * scale;
    if (threadIdx.x == 0) g_numpred[b] = total;
}

// ---------------------------------------------------------------------------
// Kernel 2: exact CIF scan (verified correct)
// ---------------------------------------------------------------------------
__global__ void k_cif() {
    int lane = threadIdx.x;
    const unsigned FULL = 0xFFFFu;
    if (lane >= BB) return;
    int b = lane;
    float integrate = 0.f, remainds = 0.f;
    int idx = 0;
    int nt1 = g_nt[b] - 1;
    int base = b * MAXP;
    int pcnt = 0;
    int   pn[6]; float pw[6]; int pc = 0;

    for (int t = 0; t < TT; t++) {
        if (t > 0) {
            if (remainds != 0.f && pc < 6) { pn[pc] = idx; pw[pc] = remainds; pc++; }
            for (int i = 0; i < pc; i++)
                if (pw[i] != 0.f && pcnt < MAXP) {
                    g_pair_n[base+pcnt] = pn[i];
                    g_pair_t[base+pcnt] = t-1;
                    g_pair_w[base+pcnt] = pw[i];
                    pcnt++;
                }
            pc = 0;
        }
        float a = g_alphas[b*TT + t];
        float alpha_needed = 1.f - integrate;
        integrate += a;
        bool ready = (integrate >= 1.f);
        if (ready) integrate -= 1.f;
        float aint = ready ? alpha_needed : a;
        pn[0] = idx; pw[0] = aint; pc = 1;
        remainds = a - aint;
        if (ready) idx = min(idx + 1, nt1);

        #pragma unroll
        for (int e = 0; e < 3; e++) {
            bool any = __any_sync(FULL, integrate >= 1.f);
            if (any) {
                bool r2 = (integrate >= 1.f);
                if (r2) integrate -= 1.f;
                float ai2 = r2 ? 1.f : remainds;
                int j;
                for (j = 0; j < pc; j++) if (pn[j] == idx) { pw[j] = ai2; break; }
                if (j == pc && pc < 6) { pn[pc] = idx; pw[pc] = ai2; pc++; }
                remainds = remainds - ai2;
                if (r2) idx = min(idx + 1, nt1);
            }
        }
    }
    for (int i = 0; i < pc; i++)
        if (pw[i] != 0.f && pcnt < MAXP) {
            g_pair_n[base+pcnt] = pn[i];
            g_pair_t[base+pcnt] = TT-1;
            g_pair_w[base+pcnt] = pw[i];
            pcnt++;
        }
    int* rp = &g_rowptr[b*(NTOK+1)];
    int p = 0;
    rp[0] = 0;
    for (int n = 0; n < NTOK; n++) {
        while (p < pcnt && g_pair_n[base+p] == n) p++;
        rp[n+1] = p;
    }
}

// ---------------------------------------------------------------------------
// Kernel 3: h1 = CIF sparse sum, written as fp16 hi/lo splits
// ---------------------------------------------------------------------------
__global__ void k_h1(const float* __restrict__ af) {
    int r = blockIdx.x;
    int b = r / NTOK, n = r % NTOK;
    int s = g_rowptr[b*(NTOK+1) + n];
    int e = g_rowptr[b*(NTOK+1) + n + 1];
    int d = threadIdx.x;
    float a0 = 0.f, a1 = 0.f, a2 = 0.f, a3 = 0.f;
    for (int p = s; p < e; p++) {
        int   t = g_pair_t[b*MAXP + p];
        float w = g_pair_w[b*MAXP + p];
        const float* row = af + ((size_t)b*TT + t)*DD;
        a0 += w * row[d];
        a1 += w * row[d + 256];
        a2 += w * row[d + 512];
        if (d + 768 < DH) a3 += w * row[d + 768];
    }
    size_t o = (size_t)r*LDH;
    __half h, l;
    split_h(a0, h, l); g_ahi[o+d]     = h; g_alo[o+d]     = l;
    split_h(a1, h, l); g_ahi[o+d+256] = h; g_alo[o+d+256] = l;
    split_h(a2, h, l); g_ahi[o+d+512] = h; g_alo[o+d+512] = l;
    if (d + 768 < DH) { split_h(a3, h, l); g_ahi[o+d+768] = h; g_alo[o+d+768] = l; }
    else { g_ahi[o+1023] = __float2half(0.f); g_alo[o+1023] = __float2half(0.f); }
}

// ---------------------------------------------------------------------------
// Kernel 3b: pad+split cif_w [1024,1023] -> fp16 hi/lo [1024,1024]
// ---------------------------------------------------------------------------
__global__ void k_padw_split(const float* __restrict__ w) {
    int i = blockIdx.x * 256 + threadIdx.x;
    int n = i >> 10, k = i & 1023;
    float v = (k < DH) ? w[(size_t)n*DH + k] : 0.f;
    __half h, l; split_h(v, h, l);
    g_bhi[i] = h; g_blo[i] = l;
}

// ---------------------------------------------------------------------------
// Kernel 3c: text_w [4096,1024] -> fp16 hi only (2-pass GEMM needs no lo)
// ---------------------------------------------------------------------------
__global__ void k_w_hi(const float* __restrict__ w) {
    int i = blockIdx.x * 256 + threadIdx.x;
    g_bhi[i] = __float2half(w[i]);
}

// ---------------------------------------------------------------------------
// Kernel 5: RMSNorm on g_h2, write normalized rows as fp16 hi/lo splits
// ---------------------------------------------------------------------------
__global__ void k_rms(const float* __restrict__ lnw) {
    int r = blockIdx.x;
    const float* hp = g_h2 + (size_t)r*DD;
    int tid = threadIdx.x;
    float v0 = hp[tid], v1 = hp[tid+256], v2 = hp[tid+512], v3 = hp[tid+768];
    __shared__ float red[256];
    red[tid] = v0*v0 + v1*v1 + v2*v2 + v3*v3;
    __syncthreads();
    for (int o = 128; o > 0; o >>= 1) {
        if (tid < o) red[tid] += red[tid + o];
        __syncthreads();
    }
    float inv = rsqrtf(red[0] * (1.0f/DD) + 1e-6f);
    size_t o = (size_t)r*DD;
    __half h, l;
    split_h(v0*inv*lnw[tid],     h, l); g_ahi[o+tid]     = h; g_alo[o+tid]     = l;
    split_h(v1*inv*lnw[tid+256], h, l); g_ahi[o+tid+256] = h; g_alo[o+tid+256] = l;
    split_h(v2*inv*lnw[tid+512], h, l); g_ahi[o+tid+512] = h; g_alo[o+tid+512] = l;
    split_h(v3*inv*lnw[tid+768], h, l); g_ahi[o+tid+768] = h; g_alo[o+tid+768] = l;
}

// ---------------------------------------------------------------------------
// fp16 multi-pass tensor-core GEMM (mma.sync.m16n8k16, pre-split operands).
// NPASS=3: C = Ah·Bh + Ah·Bl + Al·Bh   (full ~2^-22 accuracy)
// NPASS=2: C = Ah·Bh + Al·Bh           (B single fp16, ~2^-11 accuracy)
// 128x128 CTA tile, BK=32, 256 threads, warp tile 64x32.
// ---------------------------------------------------------------------------
#define ASTRIDE   40                       // smem row stride in halves (80 B)
#define TILEB     (128*ASTRIDE*2)          // 10240 B per operand-part tile

__device__ __forceinline__ void cp16(uint32_t dst, const void* src) {
    asm volatile("cp.async.cg.shared.global [%0], [%1], 16;"
                 :: "r"(dst), "l"(src) : "memory");
}
__device__ __forceinline__ void ldsm4(uint32_t r[4], uint32_t addr) {
    asm volatile("ldmatrix.sync.aligned.m8n8.x4.shared.b16 {%0,%1,%2,%3}, [%4];"
                 : "=r"(r[0]), "=r"(r[1]), "=r"(r[2]), "=r"(r[3]) : "r"(addr));
}
__device__ __forceinline__ void mma_h(float d[4], const uint32_t a[4],
                                      uint32_t b0, uint32_t b1) {
    asm volatile(
        "mma.sync.aligned.m16n8k16.row.col.f32.f16.f16.f32 "
        "{%0,%1,%2,%3}, {%4,%5,%6,%7}, {%8,%9}, {%0,%1,%2,%3};"
        : "+f"(d[0]), "+f"(d[1]), "+f"(d[2]), "+f"(d[3])
        : "r"(a[0]), "r"(a[1]), "r"(a[2]), "r"(a[3]), "r"(b0), "r"(b1));
}

template<int NPASS>
__global__ void __launch_bounds__(256)
gemm_h(int M, int K,
       const __half* __restrict__ Ah, const __half* __restrict__ Al, int lda,
       const __half* __restrict__ Bh, const __half* __restrict__ Bl, int ldb,
       const float* __restrict__ bias,
       float* __restrict__ C, int ldc)
{
    constexpr int NTILES = (NPASS == 3) ? 4 : 3;        // Ah,Al,Bh[,Bl]
    constexpr uint32_t STAGEB = NTILES * TILEB;
    extern __shared__ __align__(128) char smem[];
    uint32_t sbase = (uint32_t)__cvta_generic_to_shared(smem);

    int tid  = threadIdx.x;
    int wid  = tid >> 5, lane = tid & 31;
    int g    = lane >> 2, tig = lane & 3;
    int m0   = blockIdx.y * 128;
    int n0   = blockIdx.x * 128;
    int wm   = (wid & 1) * 64;
    int wn   = (wid >> 1) * 32;

    float acc[4][4][4];
    #pragma unroll
    for (int i = 0; i < 4; i++)
        #pragma unroll
        for (int j = 0; j < 4; j++)
            #pragma unroll
            for (int q = 0; q < 4; q++) acc[i][j][q] = 0.f;

    const int nt = K >> 5;   // K / 32

    // stage layout: [Ah | Al | Bh | Bl?], each 128 rows x 80B
    auto load_stage = [&](int s, int kt) {
        uint32_t st = sbase + (uint32_t)s * STAGEB;
        int k0 = kt << 5;
        #pragma unroll
        for (int c = tid; c < 512; c += 256) {
            int row = c >> 2, ch = (c & 3) << 4;       // ch bytes (0,16,32,48)
            int ke = k0 + (ch >> 1);
            int gm = m0 + row; if (gm >= M) gm = M - 1;
            uint32_t d = st + row*80 + ch;
            cp16(d,           Ah + (size_t)gm*lda + ke);
            cp16(d + TILEB,   Al + (size_t)gm*lda + ke);
            size_t gb = (size_t)(n0 + row)*ldb + ke;
            cp16(d + 2*TILEB, Bh + gb);
            if (NPASS == 3) cp16(d + 3*TILEB, Bl + gb);
        }
        asm volatile("cp.async.commit_group;" ::: "memory");
    };

    load_stage(0, 0);

    int quad = lane >> 3, qr = lane & 7;
    for (int kt = 0; kt < nt; kt++) {
        int buf = kt & 1;
        if (kt + 1 < nt) {
            load_stage(buf ^ 1, kt + 1);
            asm volatile("cp.async.wait_group 1;" ::: "memory");
        } else {
            asm volatile("cp.async.wait_group 0;" ::: "memory");
        }
        __syncthreads();

        uint32_t st = sbase + (uint32_t)buf * STAGEB;
        #pragma unroll
        for (int ks = 0; ks < 2; ks++) {
            int kc = ks * 16;
            uint32_t ka = (uint32_t)((kc + ((quad >> 1) << 3)) << 1);
            uint32_t arow = st + (uint32_t)(wm + ((quad & 1) << 3) + qr) * 80 + ka;
            uint32_t brow = st + 2*TILEB
                          + (uint32_t)(wn + ((quad & 1) << 3) + qr) * 80 + ka;

            uint32_t ah[4][4], al[4][4], bh[2][4], bl[2][4];
            #pragma unroll
            for (int mi = 0; mi < 4; mi++) {
                ldsm4(ah[mi], arow + mi*16*80);
                ldsm4(al[mi], arow + TILEB + mi*16*80);
            }
            #pragma unroll
            for (int nb = 0; nb < 2; nb++) {
                ldsm4(bh[nb], brow + nb*16*80);
                if (NPASS == 3) ldsm4(bl[nb], brow + TILEB + nb*16*80);
            }
            #pragma unroll
            for (int mi = 0; mi < 4; mi++)
                #pragma unroll
                for (int ni = 0; ni < 4; ni++) {
                    int nb = ni >> 1, sel = ni & 1;
                    mma_h(acc[mi][ni], ah[mi], bh[nb][sel], bh[nb][sel+2]);   // hh
                    mma_h(acc[mi][ni], al[mi], bh[nb][sel], bh[nb][sel+2]);   // lh
                    if (NPASS == 3)
                        mma_h(acc[mi][ni], ah[mi], bl[nb][sel], bl[nb][sel+2]); // hl
                }
        }
        __syncthreads();
    }

    // ---- epilogue ----
    #pragma unroll
    for (int mi = 0; mi < 4; mi++) {
        int row0 = m0 + wm + mi*16 + g;
        int row1 = row0 + 8;
        #pragma unroll
        for (int ni = 0; ni < 4; ni++) {
            int col = n0 + wn + ni*8 + 2*tig;
            float b0 = bias[col], b1 = bias[col+1];
            if (row0 < M) {
                float2 v = { acc[mi][ni][0] + b0, acc[mi][ni][1] + b1 };
                *reinterpret_cast<float2*>(C + (size_t)row0*ldc + col) = v;
            }
            if (row1 < M) {
                float2 v = { acc[mi][ni][2] + b0, acc[mi][ni][3] + b1 };
                *reinterpret_cast<float2*>(C + (size_t)row1*ldc + col) = v;
            }
        }
    }
}

// ---------------------------------------------------------------------------
// Kernel 7: optional tail outputs
// ---------------------------------------------------------------------------
__global__ void k_tail(float* __restrict__ out, int out_size) {
    int i = threadIdx.x;
    if (i < BB && out_size >= MM*DTXT + 2*BB) {
        out[MM*DTXT + i]      = (float)g_nt[i];
        out[MM*DTXT + BB + i] = g_numpred[i];
    }
}

// ---------------------------------------------------------------------------
extern "C" void kernel_launch(void* const* d_in, const int* in_sizes, int n_in,
                              void* d_out, int out_size) {
    const float* af     = (const float*)d_in[0];
    const float* cif_w  = (const float*)d_in[1];
    const float* cif_b  = (const float*)d_in[2];
    const float* ln_w   = (const float*)d_in[3];
    const float* text_w = (const float*)d_in[4];
    const float* text_b = (const float*)d_in[5];
    const void*  nf     = d_in[6];
    const void*  nt     = d_in[7];
    float* out = (float*)d_out;

    void *p_h2=0, *p_ahi=0, *p_alo=0, *p_bhi=0, *p_blo=0;
    cudaGetSymbolAddress(&p_h2,  g_h2);
    cudaGetSymbolAddress(&p_ahi, g_ahi);
    cudaGetSymbolAddress(&p_alo, g_alo);
    cudaGetSymbolAddress(&p_bhi, g_bhi);
    cudaGetSymbolAddress(&p_blo, g_blo);

    const int SMEM3 = 2 * 4 * TILEB;   // 81920
    const int SMEM2 = 2 * 3 * TILEB;   // 61440
    cudaFuncSetAttribute(gemm_h<3>, cudaFuncAttributeMaxDynamicSharedMemorySize, SMEM3);
    cudaFuncSetAttribute(gemm_h<2>, cudaFuncAttributeMaxDynamicSharedMemorySize, SMEM2);

    k_detect<<<1, 1>>>(nf, nt);
    k_alphas<<<BB, 256>>>(af);
    k_cif<<<1, 32>>>();
    k_h1<<<MM, 256>>>(af);                          // -> g_ahi/g_alo (fp16)
    k_padw_split<<<(DD*DD)/256, 256>>>(cif_w);      // -> g_bhi/g_blo (fp16)

    // cif_proj: 3-pass (full accuracy): [6000,1024] x [1024,1024]^T -> g_h2
    {
        dim3 grid(DD/128, (MM + 127)/128);
        gemm_h<3><<<grid, 256, SMEM3>>>(MM, 1024,
            (const __half*)p_ahi, (const __half*)p_alo, LDH,
            (const __half*)p_bhi, (const __half*)p_blo, 1024,
            cif_b, (float*)p_h2, DD);
    }
    k_rms<<<MM, 256>>>(ln_w);                       // g_h2 -> g_ahi/g_alo
    k_w_hi<<<(DTXT*DD)/256, 256>>>(text_w);         // -> g_bhi only

    // text_proj: 2-pass (A split, B fp16): [6000,1024] x [4096,1024]^T -> out
    {
        dim3 grid(DTXT/128, (MM + 127)/128);
        gemm_h<2><<<grid, 256, SMEM2>>>(MM, 1024,
            (const __half*)p_ahi, (const __half*)p_alo, DD,
            (const __half*)p_bhi, (const __half*)p_blo, DD,
            text_b, out, DTXT);
    }
    k_tail<<<1, 32>>>(out, out_size);
}

// round 7
// speedup vs baseline: 2.8486x; 1.1742x over previous
#include <cuda_runtime.h>
#include <cuda_fp16.h>
#include <math.h>
#include <stdint.h>

// ---------------------------------------------------------------------------
// Problem dimensions (fixed by the dataset)
// ---------------------------------------------------------------------------
#define BB   16
#define TT   1500
#define DD   1024
#define DH   1023
#define DTXT 4096
#define NTOK 375
#define MM   (BB*NTOK)     // 6000
#define MAXP 12288
#define LDH  1024

// ---------------------------------------------------------------------------
// Device scratch
// ---------------------------------------------------------------------------
__device__ float g_alphas[BB*TT];
__device__ float g_numpred[BB];
__device__ int   g_nf[BB];
__device__ int   g_nt[BB];
__device__ int   g_pair_n[BB*MAXP];
__device__ int   g_pair_t[BB*MAXP];
__device__ float g_pair_w[BB*MAXP];
__device__ int   g_rowptr[BB*(NTOK+1)];
__device__ float g_h2 [(size_t)MM*DD];          // cif_proj out
__device__ __half g_ahi[(size_t)MM*LDH];        // A hi
__device__ __half g_alo[(size_t)MM*LDH];        // A lo (cif_proj only)
__device__ __half g_bhi[(size_t)DTXT*DD];       // B hi

// ---------------------------------------------------------------------------
// fp16 split: x = hi + lo + O(2^-22 x)
// ---------------------------------------------------------------------------
__device__ __forceinline__ void split_h(float x, __half& h, __half& l) {
    h = __float2half(x);
    l = __float2half(x - __half2float(h));
}

// ---------------------------------------------------------------------------
// Kernel 0: int64/int32 detection
// ---------------------------------------------------------------------------
__global__ void k_detect(const void* nf_raw, const void* nt_raw) {
    const int* a = (const int*)nf_raw;
    const int* b = (const int*)nt_raw;
    bool is64 = (a[1] == 0) && (a[3] == 0) && (a[5] == 0);
    for (int i = 0; i < BB; i++) {
        if (is64) {
            g_nf[i] = (int)((const long long*)nf_raw)[i];
            g_nt[i] = (int)((const long long*)nt_raw)[i];
        } else {
            g_nf[i] = a[i];
            g_nt[i] = b[i];
        }
    }
}

// ---------------------------------------------------------------------------
// Kernel 1: masked sigmoid, per-batch sum, scale
// ---------------------------------------------------------------------------
__global__ void k_alphas(const float* __restrict__ af) {
    int b = blockIdx.x;
    __shared__ float sh[TT];
    __shared__ float red[256];
    int nf = g_nf[b];
    float s = 0.f;
    for (int t = threadIdx.x; t < TT; t += 256) {
        float x  = af[((size_t)b*TT + t)*DD + (DD-1)];
        float sg = 1.0f / (1.0f + expf(-x));
        if (t >= nf) sg = 0.f;
        sh[t] = sg;
        s += sg;
    }
    red[threadIdx.x] = s;
    __syncthreads();
    for (int o = 128; o > 0; o >>= 1) {
        if (threadIdx.x < o) red[threadIdx.x] += red[threadIdx.x + o];
        __syncthreads();
    }
    float total = red[0];
    float scale = (float)g_nt[b] / total;
    for (int t = threadIdx.x; t < TT; t += 256)
        g_alphas[b*TT + t] = sh[t] * scale;
    if (threadIdx.x == 0) g_numpred[b] = total;
}

// ---------------------------------------------------------------------------
// Kernel 2: exact CIF scan (verified correct)
// ---------------------------------------------------------------------------
__global__ void k_cif() {
    int lane = threadIdx.x;
    const unsigned FULL = 0xFFFFu;
    if (lane >= BB) return;
    int b = lane;
    float integrate = 0.f, remainds = 0.f;
    int idx = 0;
    int nt1 = g_nt[b] - 1;
    int base = b * MAXP;
    int pcnt = 0;
    int   pn[6]; float pw[6]; int pc = 0;

    for (int t = 0; t < TT; t++) {
        if (t > 0) {
            if (remainds != 0.f && pc < 6) { pn[pc] = idx; pw[pc] = remainds; pc++; }
            for (int i = 0; i < pc; i++)
                if (pw[i] != 0.f && pcnt < MAXP) {
                    g_pair_n[base+pcnt] = pn[i];
                    g_pair_t[base+pcnt] = t-1;
                    g_pair_w[base+pcnt] = pw[i];
                    pcnt++;
                }
            pc = 0;
        }
        float a = g_alphas[b*TT + t];
        float alpha_needed = 1.f - integrate;
        integrate += a;
        bool ready = (integrate >= 1.f);
        if (ready) integrate -= 1.f;
        float aint = ready ? alpha_needed : a;
        pn[0] = idx; pw[0] = aint; pc = 1;
        remainds = a - aint;
        if (ready) idx = min(idx + 1, nt1);

        #pragma unroll
        for (int e = 0; e < 3; e++) {
            bool any = __any_sync(FULL, integrate >= 1.f);
            if (any) {
                bool r2 = (integrate >= 1.f);
                if (r2) integrate -= 1.f;
                float ai2 = r2 ? 1.f : remainds;
                int j;
                for (j = 0; j < pc; j++) if (pn[j] == idx) { pw[j] = ai2; break; }
                if (j == pc && pc < 6) { pn[pc] = idx; pw[pc] = ai2; pc++; }
                remainds = remainds - ai2;
                if (r2) idx = min(idx + 1, nt1);
            }
        }
    }
    for (int i = 0; i < pc; i++)
        if (pw[i] != 0.f && pcnt < MAXP) {
            g_pair_n[base+pcnt] = pn[i];
            g_pair_t[base+pcnt] = TT-1;
            g_pair_w[base+pcnt] = pw[i];
            pcnt++;
        }
    int* rp = &g_rowptr[b*(NTOK+1)];
    int p = 0;
    rp[0] = 0;
    for (int n = 0; n < NTOK; n++) {
        while (p < pcnt && g_pair_n[base+p] == n) p++;
        rp[n+1] = p;
    }
}

// ---------------------------------------------------------------------------
// Kernel 3: h1 = CIF sparse sum, written as fp16 hi/lo splits
// ---------------------------------------------------------------------------
__global__ void k_h1(const float* __restrict__ af) {
    int r = blockIdx.x;
    int b = r / NTOK, n = r % NTOK;
    int s = g_rowptr[b*(NTOK+1) + n];
    int e = g_rowptr[b*(NTOK+1) + n + 1];
    int d = threadIdx.x;
    float a0 = 0.f, a1 = 0.f, a2 = 0.f, a3 = 0.f;
    for (int p = s; p < e; p++) {
        int   t = g_pair_t[b*MAXP + p];
        float w = g_pair_w[b*MAXP + p];
        const float* row = af + ((size_t)b*TT + t)*DD;
        a0 += w * row[d];
        a1 += w * row[d + 256];
        a2 += w * row[d + 512];
        if (d + 768 < DH) a3 += w * row[d + 768];
    }
    size_t o = (size_t)r*LDH;
    __half h, l;
    split_h(a0, h, l); g_ahi[o+d]     = h; g_alo[o+d]     = l;
    split_h(a1, h, l); g_ahi[o+d+256] = h; g_alo[o+d+256] = l;
    split_h(a2, h, l); g_ahi[o+d+512] = h; g_alo[o+d+512] = l;
    if (d + 768 < DH) { split_h(a3, h, l); g_ahi[o+d+768] = h; g_alo[o+d+768] = l; }
    else { g_ahi[o+1023] = __float2half(0.f); g_alo[o+1023] = __float2half(0.f); }
}

// ---------------------------------------------------------------------------
// Kernel 3b: pad cif_w [1024,1023] -> fp16 hi [1024,1024]
// ---------------------------------------------------------------------------
__global__ void k_padw_hi(const float* __restrict__ w) {
    int i = blockIdx.x * 256 + threadIdx.x;
    int n = i >> 10, k = i & 1023;
    float v = (k < DH) ? w[(size_t)n*DH + k] : 0.f;
    g_bhi[i] = __float2half(v);
}

// ---------------------------------------------------------------------------
// Kernel 3c: text_w [4096,1024] -> fp16 hi
// ---------------------------------------------------------------------------
__global__ void k_w_hi(const float* __restrict__ w) {
    int i = blockIdx.x * 256 + threadIdx.x;
    g_bhi[i] = __float2half(w[i]);
}

// ---------------------------------------------------------------------------
// Kernel 5: RMSNorm on g_h2, write normalized rows as fp16 hi only
// ---------------------------------------------------------------------------
__global__ void k_rms(const float* __restrict__ lnw) {
    int r = blockIdx.x;
    const float* hp = g_h2 + (size_t)r*DD;
    int tid = threadIdx.x;
    float v0 = hp[tid], v1 = hp[tid+256], v2 = hp[tid+512], v3 = hp[tid+768];
    __shared__ float red[256];
    red[tid] = v0*v0 + v1*v1 + v2*v2 + v3*v3;
    __syncthreads();
    for (int o = 128; o > 0; o >>= 1) {
        if (tid < o) red[tid] += red[tid + o];
        __syncthreads();
    }
    float inv = rsqrtf(red[0] * (1.0f/DD) + 1e-6f);
    size_t o = (size_t)r*DD;
    g_ahi[o+tid]     = __float2half(v0*inv*lnw[tid]);
    g_ahi[o+tid+256] = __float2half(v1*inv*lnw[tid+256]);
    g_ahi[o+tid+512] = __float2half(v2*inv*lnw[tid+512]);
    g_ahi[o+tid+768] = __float2half(v3*inv*lnw[tid+768]);
}

// ---------------------------------------------------------------------------
// fp16 tensor-core GEMM (mma.sync.m16n8k16, pre-split operands).
// NPASS=2: C = Ah·Bh + Al·Bh   (A split, ~A-exact; B fp16-rounded)
// NPASS=1: C = Ah·Bh           (both plain fp16)
// 128x128 CTA tile, BK=32, 256 threads, warp tile 64x32.
// ---------------------------------------------------------------------------
#define ASTRIDE   40                       // smem row stride in halves (80 B)
#define TILEB     (128*ASTRIDE*2)          // 10240 B per operand-part tile

__device__ __forceinline__ void cp16(uint32_t dst, const void* src) {
    asm volatile("cp.async.cg.shared.global [%0], [%1], 16;"
                 :: "r"(dst), "l"(src) : "memory");
}
__device__ __forceinline__ void ldsm4(uint32_t r[4], uint32_t addr) {
    asm volatile("ldmatrix.sync.aligned.m8n8.x4.shared.b16 {%0,%1,%2,%3}, [%4];"
                 : "=r"(r[0]), "=r"(r[1]), "=r"(r[2]), "=r"(r[3]) : "r"(addr));
}
__device__ __forceinline__ void mma_h(float d[4], const uint32_t a[4],
                                      uint32_t b0, uint32_t b1) {
    asm volatile(
        "mma.sync.aligned.m16n8k16.row.col.f32.f16.f16.f32 "
        "{%0,%1,%2,%3}, {%4,%5,%6,%7}, {%8,%9}, {%0,%1,%2,%3};"
        : "+f"(d[0]), "+f"(d[1]), "+f"(d[2]), "+f"(d[3])
        : "r"(a[0]), "r"(a[1]), "r"(a[2]), "r"(a[3]), "r"(b0), "r"(b1));
}

template<int NPASS>   // 1: A plain; 2: A hi/lo split
__global__ void __launch_bounds__(256)
gemm_h(int M, int K,
       const __half* __restrict__ Ah, const __half* __restrict__ Al, int lda,
       const __half* __restrict__ Bh, int ldb,
       const float* __restrict__ bias,
       float* __restrict__ C, int ldc)
{
    constexpr int NA = (NPASS == 2) ? 2 : 1;      // A tiles
    constexpr int NTILES = NA + 1;                // + Bh
    constexpr uint32_t STAGEB = NTILES * TILEB;
    extern __shared__ __align__(128) char smem[];
    uint32_t sbase = (uint32_t)__cvta_generic_to_shared(smem);

    int tid  = threadIdx.x;
    int wid  = tid >> 5, lane = tid & 31;
    int g    = lane >> 2, tig = lane & 3;
    int m0   = blockIdx.y * 128;
    int n0   = blockIdx.x * 128;
    int wm   = (wid & 1) * 64;
    int wn   = (wid >> 1) * 32;

    float acc[4][4][4];
    #pragma unroll
    for (int i = 0; i < 4; i++)
        #pragma unroll
        for (int j = 0; j < 4; j++)
            #pragma unroll
            for (int q = 0; q < 4; q++) acc[i][j][q] = 0.f;

    const int nt = K >> 5;   // K / 32

    // stage layout: [Ah | Al? | Bh], each 128 rows x 80B
    auto load_stage = [&](int s, int kt) {
        uint32_t st = sbase + (uint32_t)s * STAGEB;
        int k0 = kt << 5;
        #pragma unroll
        for (int c = tid; c < 512; c += 256) {
            int row = c >> 2, ch = (c & 3) << 4;       // ch bytes (0,16,32,48)
            int ke = k0 + (ch >> 1);
            int gm = m0 + row; if (gm >= M) gm = M - 1;
            uint32_t d = st + row*80 + ch;
            cp16(d, Ah + (size_t)gm*lda + ke);
            if (NPASS == 2) cp16(d + TILEB, Al + (size_t)gm*lda + ke);
            size_t gb = (size_t)(n0 + row)*ldb + ke;
            cp16(d + NA*TILEB, Bh + gb);
        }
        asm volatile("cp.async.commit_group;" ::: "memory");
    };

    load_stage(0, 0);

    int quad = lane >> 3, qr = lane & 7;
    for (int kt = 0; kt < nt; kt++) {
        int buf = kt & 1;
        if (kt + 1 < nt) {
            load_stage(buf ^ 1, kt + 1);
            asm volatile("cp.async.wait_group 1;" ::: "memory");
        } else {
            asm volatile("cp.async.wait_group 0;" ::: "memory");
        }
        __syncthreads();

        uint32_t st = sbase + (uint32_t)buf * STAGEB;
        #pragma unroll
        for (int ks = 0; ks < 2; ks++) {
            int kc = ks * 16;
            uint32_t ka = (uint32_t)((kc + ((quad >> 1) << 3)) << 1);
            uint32_t arow = st + (uint32_t)(wm + ((quad & 1) << 3) + qr) * 80 + ka;
            uint32_t brow = st + NA*TILEB
                          + (uint32_t)(wn + ((quad & 1) << 3) + qr) * 80 + ka;

            uint32_t ah[4][4], al[4][4], bh[2][4];
            #pragma unroll
            for (int mi = 0; mi < 4; mi++) {
                ldsm4(ah[mi], arow + mi*16*80);
                if (NPASS == 2) ldsm4(al[mi], arow + TILEB + mi*16*80);
            }
            #pragma unroll
            for (int nb = 0; nb < 2; nb++)
                ldsm4(bh[nb], brow + nb*16*80);

            #pragma unroll
            for (int mi = 0; mi < 4; mi++)
                #pragma unroll
                for (int ni = 0; ni < 4; ni++) {
                    int nb = ni >> 1, sel = ni & 1;
                    mma_h(acc[mi][ni], ah[mi], bh[nb][sel], bh[nb][sel+2]);      // hh
                    if (NPASS == 2)
                        mma_h(acc[mi][ni], al[mi], bh[nb][sel], bh[nb][sel+2]);  // lh
                }
        }
        __syncthreads();
    }

    // ---- epilogue ----
    #pragma unroll
    for (int mi = 0; mi < 4; mi++) {
        int row0 = m0 + wm + mi*16 + g;
        int row1 = row0 + 8;
        #pragma unroll
        for (int ni = 0; ni < 4; ni++) {
            int col = n0 + wn + ni*8 + 2*tig;
            float b0 = bias[col], b1 = bias[col+1];
            if (row0 < M) {
                float2 v = { acc[mi][ni][0] + b0, acc[mi][ni][1] + b1 };
                *reinterpret_cast<float2*>(C + (size_t)row0*ldc + col) = v;
            }
            if (row1 < M) {
                float2 v = { acc[mi][ni][2] + b0, acc[mi][ni][3] + b1 };
                *reinterpret_cast<float2*>(C + (size_t)row1*ldc + col) = v;
            }
        }
    }
}

// ---------------------------------------------------------------------------
// Kernel 7: optional tail outputs
// ---------------------------------------------------------------------------
__global__ void k_tail(float* __restrict__ out, int out_size) {
    int i = threadIdx.x;
    if (i < BB && out_size >= MM*DTXT + 2*BB) {
        out[MM*DTXT + i]      = (float)g_nt[i];
        out[MM*DTXT + BB + i] = g_numpred[i];
    }
}

// ---------------------------------------------------------------------------
extern "C" void kernel_launch(void* const* d_in, const int* in_sizes, int n_in,
                              void* d_out, int out_size) {
    const float* af     = (const float*)d_in[0];
    const float* cif_w  = (const float*)d_in[1];
    const float* cif_b  = (const float*)d_in[2];
    const float* ln_w   = (const float*)d_in[3];
    const float* text_w = (const float*)d_in[4];
    const float* text_b = (const float*)d_in[5];
    const void*  nf     = d_in[6];
    const void*  nt     = d_in[7];
    float* out = (float*)d_out;

    void *p_h2=0, *p_ahi=0, *p_alo=0, *p_bhi=0;
    cudaGetSymbolAddress(&p_h2,  g_h2);
    cudaGetSymbolAddress(&p_ahi, g_ahi);
    cudaGetSymbolAddress(&p_alo, g_alo);
    cudaGetSymbolAddress(&p_bhi, g_bhi);

    const int SMEM2 = 2 * 3 * TILEB;   // 61440 (A split)
    const int SMEM1 = 2 * 2 * TILEB;   // 40960 (A plain)
    cudaFuncSetAttribute(gemm_h<2>, cudaFuncAttributeMaxDynamicSharedMemorySize, SMEM2);
    cudaFuncSetAttribute(gemm_h<1>, cudaFuncAttributeMaxDynamicSharedMemorySize, SMEM1);

    k_detect<<<1, 1>>>(nf, nt);
    k_alphas<<<BB, 256>>>(af);
    k_cif<<<1, 32>>>();
    k_h1<<<MM, 256>>>(af);                          // -> g_ahi/g_alo (fp16)
    k_padw_hi<<<(DD*DD)/256, 256>>>(cif_w);         // -> g_bhi (fp16)

    // cif_proj: 2-pass (A split, B fp16): [6000,1024] x [1024,1024]^T -> g_h2
    {
        dim3 grid(DD/128, (MM + 127)/128);
        gemm_h<2><<<grid, 256, SMEM2>>>(MM, 1024,
            (const __half*)p_ahi, (const __half*)p_alo, LDH,
            (const __half*)p_bhi, 1024,
            cif_b, (float*)p_h2, DD);
    }
    k_rms<<<MM, 256>>>(ln_w);                       // g_h2 -> g_ahi (hi only)
    k_w_hi<<<(DTXT*DD)/256, 256>>>(text_w);         // -> g_bhi

    // text_proj: 1-pass fp16: [6000,1024] x [4096,1024]^T -> out
    {
        dim3 grid(DTXT/128, (MM + 127)/128);
        gemm_h<1><<<grid, 256, SMEM1>>>(MM, 1024,
            (const __half*)p_ahi, (const __half*)p_alo, DD,
            (const __half*)p_bhi, DD,
            text_b, out, DTXT);
    }
    k_tail<<<1, 32>>>(out, out_size);
}

// round 8
// speedup vs baseline: 3.6575x; 1.2840x over previous
#include <cuda_runtime.h>
#include <cuda_fp16.h>
#include <math.h>
#include <stdint.h>

// ---------------------------------------------------------------------------
// Problem dimensions (fixed by the dataset)
// ---------------------------------------------------------------------------
#define BB   16
#define TT   1500
#define DD   1024
#define DH   1023
#define DTXT 4096
#define NTOK 375
#define MM   (BB*NTOK)     // 6000
#define MAXP 12288
#define LDH  1024

// ---------------------------------------------------------------------------
// Device scratch
// ---------------------------------------------------------------------------
__device__ float g_alphas[BB*TT];
__device__ float g_numpred[BB];
__device__ int   g_nf[BB];
__device__ int   g_nt[BB];
__device__ int   g_pair_n[BB*MAXP];
__device__ int   g_pair_t[BB*MAXP];
__device__ float g_pair_w[BB*MAXP];
__device__ int   g_rowptr[BB*(NTOK+1)];
__device__ float g_h2 [(size_t)MM*DD];          // cif_proj out
__device__ __half g_ahi[(size_t)MM*LDH];        // A hi
__device__ __half g_alo[(size_t)MM*LDH];        // A lo (cif_proj only)
__device__ __half g_bhi[(size_t)DTXT*DD];       // B hi

// ---------------------------------------------------------------------------
// fp16 split: x = hi + lo + O(2^-22 x)
// ---------------------------------------------------------------------------
__device__ __forceinline__ void split_h(float x, __half& h, __half& l) {
    h = __float2half(x);
    l = __float2half(x - __half2float(h));
}

// ---------------------------------------------------------------------------
// Kernel 0: int64/int32 detection
// ---------------------------------------------------------------------------
__global__ void k_detect(const void* nf_raw, const void* nt_raw) {
    const int* a = (const int*)nf_raw;
    const int* b = (const int*)nt_raw;
    bool is64 = (a[1] == 0) && (a[3] == 0) && (a[5] == 0);
    for (int i = 0; i < BB; i++) {
        if (is64) {
            g_nf[i] = (int)((const long long*)nf_raw)[i];
            g_nt[i] = (int)((const long long*)nt_raw)[i];
        } else {
            g_nf[i] = a[i];
            g_nt[i] = b[i];
        }
    }
}

// ---------------------------------------------------------------------------
// Kernel 1: masked sigmoid, per-batch sum, scale
// ---------------------------------------------------------------------------
__global__ void k_alphas(const float* __restrict__ af) {
    int b = blockIdx.x;
    __shared__ float sh[TT];
    __shared__ float red[256];
    int nf = g_nf[b];
    float s = 0.f;
    for (int t = threadIdx.x; t < TT; t += 256) {
        float x  = af[((size_t)b*TT + t)*DD + (DD-1)];
        float sg = 1.0f / (1.0f + expf(-x));
        if (t >= nf) sg = 0.f;
        sh[t] = sg;
        s += sg;
    }
    red[threadIdx.x] = s;
    __syncthreads();
    for (int o = 128; o > 0; o >>= 1) {
        if (threadIdx.x < o) red[threadIdx.x] += red[threadIdx.x + o];
        __syncthreads();
    }
    float total = red[0];
    float scale = (float)g_nt[b] / total;
    for (int t = threadIdx.x; t < TT; t += 256)
        g_alphas[b*TT + t] = sh[t] * scale;
    if (threadIdx.x == 0) g_numpred[b] = total;
}

// ---------------------------------------------------------------------------
// Kernel 2 (v2): exact CIF scan, smem-staged, register-resident pair buffer.
//  - alphas staged to smem by 128 threads (coalesced), scan reads LDS only
//  - pn/pw accessed via fully unrolled fixed-bound loops => registers
//  - rowptr built from smem "last emission index" table (no global re-read)
// Semantics identical to the verified scan.
// ---------------------------------------------------------------------------
#define CIF_SMEM (BB*TT*4 + BB*(NTOK+1)*4)   // 96000 + 24064 = 120064 B

__global__ void k_cif2() {
    extern __shared__ char cs[];
    float* sal  = (float*)cs;                   // [BB*TT]
    int*   slast = (int*)(cs + BB*TT*4);        // [BB*(NTOK+1)]
    int tid = threadIdx.x;

    // phase 1: stage alphas + zero slast
    for (int i = tid; i < BB*TT; i += 128) sal[i] = g_alphas[i];
    for (int i = tid; i < BB*(NTOK+1); i += 128) slast[i] = 0;
    __syncthreads();

    if (tid < BB) {
        const unsigned FULL = 0xFFFFu;
        int b = tid;
        float integrate = 0.f, remainds = 0.f;
        int idx = 0;
        int nt1 = g_nt[b] - 1;
        int base = b * MAXP;
        int pcnt = 0;
        int   pn[6]; float pw[6]; int pc = 0;
        const float* al = sal + b*TT;
        int* lrow = slast + b*(NTOK+1);

        for (int t = 0; t < TT; t++) {
            if (t > 0) {
                // append remainder (scatter-add of frame t-1)
                if (remainds != 0.f) {
                    #pragma unroll
                    for (int j = 0; j < 6; j++)
                        if (j == pc) { pn[j] = idx; pw[j] = remainds; }
                    if (pc < 6) pc++;
                }
                // flush pairs of frame t-1
                #pragma unroll
                for (int i = 0; i < 6; i++) {
                    if (i < pc && pw[i] != 0.f && pcnt < MAXP) {
                        g_pair_n[base+pcnt] = pn[i];
                        g_pair_t[base+pcnt] = t-1;
                        g_pair_w[base+pcnt] = pw[i];
                        lrow[pn[i]] = pcnt + 1;
                        pcnt++;
                    }
                }
                pc = 0;
            }
            float a = al[t];
            float alpha_needed = 1.f - integrate;
            integrate += a;
            bool ready = (integrate >= 1.f);
            if (ready) integrate -= 1.f;
            float aint = ready ? alpha_needed : a;
            pn[0] = idx; pw[0] = aint; pc = 1;
            remainds = a - aint;
            if (ready) idx = min(idx + 1, nt1);

            #pragma unroll
            for (int e = 0; e < 3; e++) {
                bool any = __any_sync(FULL, integrate >= 1.f);
                if (any) {
                    bool r2 = (integrate >= 1.f);
                    if (r2) integrate -= 1.f;
                    float ai2 = r2 ? 1.f : remainds;
                    // overwrite-if-present else append (register-resident)
                    bool found = false;
                    #pragma unroll
                    for (int j = 0; j < 6; j++)
                        if (j < pc && pn[j] == idx && !found) { pw[j] = ai2; found = true; }
                    if (!found) {
                        #pragma unroll
                        for (int j = 0; j < 6; j++)
                            if (j == pc) { pn[j] = idx; pw[j] = ai2; }
                        if (pc < 6) pc++;
                    }
                    remainds = remainds - ai2;
                    if (r2) idx = min(idx + 1, nt1);
                }
            }
        }
        // final frame T-1: flush WITHOUT its remainder
        #pragma unroll
        for (int i = 0; i < 6; i++) {
            if (i < pc && pw[i] != 0.f && pcnt < MAXP) {
                g_pair_n[base+pcnt] = pn[i];
                g_pair_t[base+pcnt] = TT-1;
                g_pair_w[base+pcnt] = pw[i];
                lrow[pn[i]] = pcnt + 1;
                pcnt++;
            }
        }
        // rowptr from last-emission table (own lane's writes only)
        int* rp = &g_rowptr[b*(NTOK+1)];
        rp[0] = 0;
        int p = 0;
        for (int n = 0; n < NTOK; n++) {
            int v = lrow[n];
            if (v > 0) p = v;
            rp[n+1] = p;
        }
    }
}

// ---------------------------------------------------------------------------
// Kernel 3: h1 = CIF sparse sum, written as fp16 hi/lo splits
// ---------------------------------------------------------------------------
__global__ void k_h1(const float* __restrict__ af) {
    int r = blockIdx.x;
    int b = r / NTOK, n = r % NTOK;
    int s = g_rowptr[b*(NTOK+1) + n];
    int e = g_rowptr[b*(NTOK+1) + n + 1];
    int d = threadIdx.x;
    float a0 = 0.f, a1 = 0.f, a2 = 0.f, a3 = 0.f;
    for (int p = s; p < e; p++) {
        int   t = g_pair_t[b*MAXP + p];
        float w = g_pair_w[b*MAXP + p];
        const float* row = af + ((size_t)b*TT + t)*DD;
        a0 += w * row[d];
        a1 += w * row[d + 256];
        a2 += w * row[d + 512];
        if (d + 768 < DH) a3 += w * row[d + 768];
    }
    size_t o = (size_t)r*LDH;
    __half h, l;
    split_h(a0, h, l); g_ahi[o+d]     = h; g_alo[o+d]     = l;
    split_h(a1, h, l); g_ahi[o+d+256] = h; g_alo[o+d+256] = l;
    split_h(a2, h, l); g_ahi[o+d+512] = h; g_alo[o+d+512] = l;
    if (d + 768 < DH) { split_h(a3, h, l); g_ahi[o+d+768] = h; g_alo[o+d+768] = l; }
    else { g_ahi[o+1023] = __float2half(0.f); g_alo[o+1023] = __float2half(0.f); }
}

// ---------------------------------------------------------------------------
// Kernel 3b: pad cif_w [1024,1023] -> fp16 hi [1024,1024]
// ---------------------------------------------------------------------------
__global__ void k_padw_hi(const float* __restrict__ w) {
    int i = blockIdx.x * 256 + threadIdx.x;
    int n = i >> 10, k = i & 1023;
    float v = (k < DH) ? w[(size_t)n*DH + k] : 0.f;
    g_bhi[i] = __float2half(v);
}

// ---------------------------------------------------------------------------
// Kernel 3c: text_w [4096,1024] -> fp16 hi
// ---------------------------------------------------------------------------
__global__ void k_w_hi(const float* __restrict__ w) {
    int i = blockIdx.x * 256 + threadIdx.x;
    g_bhi[i] = __float2half(w[i]);
}

// ---------------------------------------------------------------------------
// Kernel 5: RMSNorm on g_h2, write normalized rows as fp16 hi only
// ---------------------------------------------------------------------------
__global__ void k_rms(const float* __restrict__ lnw) {
    int r = blockIdx.x;
    const float* hp = g_h2 + (size_t)r*DD;
    int tid = threadIdx.x;
    float v0 = hp[tid], v1 = hp[tid+256], v2 = hp[tid+512], v3 = hp[tid+768];
    __shared__ float red[256];
    red[tid] = v0*v0 + v1*v1 + v2*v2 + v3*v3;
    __syncthreads();
    for (int o = 128; o > 0; o >>= 1) {
        if (tid < o) red[tid] += red[tid + o];
        __syncthreads();
    }
    float inv = rsqrtf(red[0] * (1.0f/DD) + 1e-6f);
    size_t o = (size_t)r*DD;
    g_ahi[o+tid]     = __float2half(v0*inv*lnw[tid]);
    g_ahi[o+tid+256] = __float2half(v1*inv*lnw[tid+256]);
    g_ahi[o+tid+512] = __float2half(v2*inv*lnw[tid+512]);
    g_ahi[o+tid+768] = __float2half(v3*inv*lnw[tid+768]);
}

// ---------------------------------------------------------------------------
// fp16 tensor-core GEMM (mma.sync.m16n8k16, pre-split operands).
// NPASS=2: C = Ah·Bh + Al·Bh ; NPASS=1: C = Ah·Bh
// 128x128 CTA tile, BK=32, 256 threads, warp tile 64x32.
// ---------------------------------------------------------------------------
#define ASTRIDE   40                       // smem row stride in halves (80 B)
#define TILEB     (128*ASTRIDE*2)          // 10240 B per operand-part tile

__device__ __forceinline__ void cp16(uint32_t dst, const void* src) {
    asm volatile("cp.async.cg.shared.global [%0], [%1], 16;"
                 :: "r"(dst), "l"(src) : "memory");
}
__device__ __forceinline__ void ldsm4(uint32_t r[4], uint32_t addr) {
    asm volatile("ldmatrix.sync.aligned.m8n8.x4.shared.b16 {%0,%1,%2,%3}, [%4];"
                 : "=r"(r[0]), "=r"(r[1]), "=r"(r[2]), "=r"(r[3]) : "r"(addr));
}
__device__ __forceinline__ void mma_h(float d[4], const uint32_t a[4],
                                      uint32_t b0, uint32_t b1) {
    asm volatile(
        "mma.sync.aligned.m16n8k16.row.col.f32.f16.f16.f32 "
        "{%0,%1,%2,%3}, {%4,%5,%6,%7}, {%8,%9}, {%0,%1,%2,%3};"
        : "+f"(d[0]), "+f"(d[1]), "+f"(d[2]), "+f"(d[3])
        : "r"(a[0]), "r"(a[1]), "r"(a[2]), "r"(a[3]), "r"(b0), "r"(b1));
}

template<int NPASS>   // 1: A plain; 2: A hi/lo split
__global__ void __launch_bounds__(256)
gemm_h(int M, int K,
       const __half* __restrict__ Ah, const __half* __restrict__ Al, int lda,
       const __half* __restrict__ Bh, int ldb,
       const float* __restrict__ bias,
       float* __restrict__ C, int ldc)
{
    constexpr int NA = (NPASS == 2) ? 2 : 1;
    constexpr int NTILES = NA + 1;
    constexpr uint32_t STAGEB = NTILES * TILEB;
    extern __shared__ __align__(128) char smem[];
    uint32_t sbase = (uint32_t)__cvta_generic_to_shared(smem);

    int tid  = threadIdx.x;
    int wid  = tid >> 5, lane = tid & 31;
    int g    = lane >> 2, tig = lane & 3;
    int m0   = blockIdx.y * 128;
    int n0   = blockIdx.x * 128;
    int wm   = (wid & 1) * 64;
    int wn   = (wid >> 1) * 32;

    float acc[4][4][4];
    #pragma unroll
    for (int i = 0; i < 4; i++)
        #pragma unroll
        for (int j = 0; j < 4; j++)
            #pragma unroll
            for (int q = 0; q < 4; q++) acc[i][j][q] = 0.f;

    const int nt = K >> 5;

    auto load_stage = [&](int s, int kt) {
        uint32_t st = sbase + (uint32_t)s * STAGEB;
        int k0 = kt << 5;
        #pragma unroll
        for (int c = tid; c < 512; c += 256) {
            int row = c >> 2, ch = (c & 3) << 4;
            int ke = k0 + (ch >> 1);
            int gm = m0 + row; if (gm >= M) gm = M - 1;
            uint32_t d = st + row*80 + ch;
            cp16(d, Ah + (size_t)gm*lda + ke);
            if (NPASS == 2) cp16(d + TILEB, Al + (size_t)gm*lda + ke);
            size_t gb = (size_t)(n0 + row)*ldb + ke;
            cp16(d + NA*TILEB, Bh + gb);
        }
        asm volatile("cp.async.commit_group;" ::: "memory");
    };

    load_stage(0, 0);

    int quad = lane >> 3, qr = lane & 7;
    for (int kt = 0; kt < nt; kt++) {
        int buf = kt & 1;
        if (kt + 1 < nt) {
            load_stage(buf ^ 1, kt + 1);
            asm volatile("cp.async.wait_group 1;" ::: "memory");
        } else {
            asm volatile("cp.async.wait_group 0;" ::: "memory");
        }
        __syncthreads();

        uint32_t st = sbase + (uint32_t)buf * STAGEB;
        #pragma unroll
        for (int ks = 0; ks < 2; ks++) {
            int kc = ks * 16;
            uint32_t ka = (uint32_t)((kc + ((quad >> 1) << 3)) << 1);
            uint32_t arow = st + (uint32_t)(wm + ((quad & 1) << 3) + qr) * 80 + ka;
            uint32_t brow = st + NA*TILEB
                          + (uint32_t)(wn + ((quad & 1) << 3) + qr) * 80 + ka;

            uint32_t ah[4][4], al[4][4], bh[2][4];
            #pragma unroll
            for (int mi = 0; mi < 4; mi++) {
                ldsm4(ah[mi], arow + mi*16*80);
                if (NPASS == 2) ldsm4(al[mi], arow + TILEB + mi*16*80);
            }
            #pragma unroll
            for (int nb = 0; nb < 2; nb++)
                ldsm4(bh[nb], brow + nb*16*80);

            #pragma unroll
            for (int mi = 0; mi < 4; mi++)
                #pragma unroll
                for (int ni = 0; ni < 4; ni++) {
                    int nb = ni >> 1, sel = ni & 1;
                    mma_h(acc[mi][ni], ah[mi], bh[nb][sel], bh[nb][sel+2]);
                    if (NPASS == 2)
                        mma_h(acc[mi][ni], al[mi], bh[nb][sel], bh[nb][sel+2]);
                }
        }
        __syncthreads();
    }

    #pragma unroll
    for (int mi = 0; mi < 4; mi++) {
        int row0 = m0 + wm + mi*16 + g;
        int row1 = row0 + 8;
        #pragma unroll
        for (int ni = 0; ni < 4; ni++) {
            int col = n0 + wn + ni*8 + 2*tig;
            float b0 = bias[col], b1 = bias[col+1];
            if (row0 < M) {
                float2 v = { acc[mi][ni][0] + b0, acc[mi][ni][1] + b1 };
                *reinterpret_cast<float2*>(C + (size_t)row0*ldc + col) = v;
            }
            if (row1 < M) {
                float2 v = { acc[mi][ni][2] + b0, acc[mi][ni][3] + b1 };
                *reinterpret_cast<float2*>(C + (size_t)row1*ldc + col) = v;
            }
        }
    }
}

// ---------------------------------------------------------------------------
// Kernel 7: optional tail outputs
// ---------------------------------------------------------------------------
__global__ void k_tail(float* __restrict__ out, int out_size) {
    int i = threadIdx.x;
    if (i < BB && out_size >= MM*DTXT + 2*BB) {
        out[MM*DTXT + i]      = (float)g_nt[i];
        out[MM*DTXT + BB + i] = g_numpred[i];
    }
}

// ---------------------------------------------------------------------------
extern "C" void kernel_launch(void* const* d_in, const int* in_sizes, int n_in,
                              void* d_out, int out_size) {
    const float* af     = (const float*)d_in[0];
    const float* cif_w  = (const float*)d_in[1];
    const float* cif_b  = (const float*)d_in[2];
    const float* ln_w   = (const float*)d_in[3];
    const float* text_w = (const float*)d_in[4];
    const float* text_b = (const float*)d_in[5];
    const void*  nf     = d_in[6];
    const void*  nt     = d_in[7];
    float* out = (float*)d_out;

    void *p_h2=0, *p_ahi=0, *p_alo=0, *p_bhi=0;
    cudaGetSymbolAddress(&p_h2,  g_h2);
    cudaGetSymbolAddress(&p_ahi, g_ahi);
    cudaGetSymbolAddress(&p_alo, g_alo);
    cudaGetSymbolAddress(&p_bhi, g_bhi);

    const int SMEM2 = 2 * 3 * TILEB;   // 61440 (A split)
    const int SMEM1 = 2 * 2 * TILEB;   // 40960 (A plain)
    cudaFuncSetAttribute(gemm_h<2>, cudaFuncAttributeMaxDynamicSharedMemorySize, SMEM2);
    cudaFuncSetAttribute(gemm_h<1>, cudaFuncAttributeMaxDynamicSharedMemorySize, SMEM1);
    cudaFuncSetAttribute(k_cif2,    cudaFuncAttributeMaxDynamicSharedMemorySize, CIF_SMEM);

    k_detect<<<1, 1>>>(nf, nt);
    k_alphas<<<BB, 256>>>(af);
    k_cif2<<<1, 128, CIF_SMEM>>>();
    k_h1<<<MM, 256>>>(af);                          // -> g_ahi/g_alo (fp16)
    k_padw_hi<<<(DD*DD)/256, 256>>>(cif_w);         // -> g_bhi (fp16)

    // cif_proj: 2-pass (A split, B fp16): [6000,1024] x [1024,1024]^T -> g_h2
    {
        dim3 grid(DD/128, (MM + 127)/128);
        gemm_h<2><<<grid, 256, SMEM2>>>(MM, 1024,
            (const __half*)p_ahi, (const __half*)p_alo, LDH,
            (const __half*)p_bhi, 1024,
            cif_b, (float*)p_h2, DD);
    }
    k_rms<<<MM, 256>>>(ln_w);                       // g_h2 -> g_ahi (hi only)
    k_w_hi<<<(DTXT*DD)/256, 256>>>(text_w);         // -> g_bhi

    // text_proj: 1-pass fp16: [6000,1024] x [4096,1024]^T -> out
    {
        dim3 grid(DTXT/128, (MM + 127)/128);
        gemm_h<1><<<grid, 256, SMEM1>>>(MM, 1024,
            (const __half*)p_ahi, (const __half*)p_alo, DD,
            (const __half*)p_bhi, DD,
            text_b, out, DTXT);
    }
    k_tail<<<1, 32>>>(out, out_size);
}

// round 9
// speedup vs baseline: 4.6325x; 1.2666x over previous
#include <cuda_runtime.h>
#include <cuda_fp16.h>
#include <math.h>
#include <stdint.h>

// ---------------------------------------------------------------------------
// Problem dimensions (fixed by the dataset)
// ---------------------------------------------------------------------------
#define BB   16
#define TT   1500
#define DD   1024
#define DH   1023
#define DTXT 4096
#define NTOK 375
#define MM   (BB*NTOK)     // 6000
#define MAXP 12288
#define LDH  1024

// ---------------------------------------------------------------------------
// Device scratch
// ---------------------------------------------------------------------------
__device__ float g_numpred[BB];
__device__ int   g_nf[BB];
__device__ int   g_nt[BB];
__device__ int4  g_pairs[BB*MAXP];              // {n, t, w_bits, 0}
__device__ int   g_rowptr[BB*(NTOK+1)];
__device__ float g_h2 [(size_t)MM*DD];          // cif_proj out
__device__ __half g_ahi[(size_t)MM*LDH];        // A hi
__device__ __half g_alo[(size_t)MM*LDH];        // A lo (cif_proj only)
__device__ __half g_bhi[(size_t)DTXT*DD];       // B hi

// ---------------------------------------------------------------------------
// fp16 split: x = hi + lo + O(2^-22 x)
// ---------------------------------------------------------------------------
__device__ __forceinline__ void split_h(float x, __half& h, __half& l) {
    h = __float2half(x);
    l = __float2half(x - __half2float(h));
}

// ---------------------------------------------------------------------------
// Kernel 0: int64/int32 detection
// ---------------------------------------------------------------------------
__global__ void k_detect(const void* nf_raw, const void* nt_raw) {
    const int* a = (const int*)nf_raw;
    const int* b = (const int*)nt_raw;
    bool is64 = (a[1] == 0) && (a[3] == 0) && (a[5] == 0);
    for (int i = 0; i < BB; i++) {
        if (is64) {
            g_nf[i] = (int)((const long long*)nf_raw)[i];
            g_nt[i] = (int)((const long long*)nt_raw)[i];
        } else {
            g_nf[i] = a[i];
            g_nt[i] = b[i];
        }
    }
}

// ---------------------------------------------------------------------------
// Kernel CIF (fused): sigmoid+mask+sum+scale into smem, exact serial scan
// with fast/slow path, packed pair emission, rowptr build.
// 256 threads; scan runs on lanes 0..15 of warp 0.
// ---------------------------------------------------------------------------
#define CIF_SMEM (BB*TT*4 + BB*(NTOK+1)*4)   // 96000 + 24064 = 120064 B

__global__ void __launch_bounds__(256) k_cif3(const float* __restrict__ af) {
    extern __shared__ char cs[];
    float* sal   = (float*)cs;                  // [BB*TT]
    int*   slast = (int*)(cs + BB*TT*4);        // [BB*(NTOK+1)]
    __shared__ float red[256];
    __shared__ float s_scale[BB];
    int tid = threadIdx.x;

    // ---- phase A: alphas = sigmoid(af[...,-1]) * mask; per-batch sum; scale
    for (int b = 0; b < BB; b++) {
        int nf = g_nf[b];
        float s = 0.f;
        for (int t = tid; t < TT; t += 256) {
            float x  = af[((size_t)b*TT + t)*DD + (DD-1)];
            float sg = 1.0f / (1.0f + expf(-x));
            if (t >= nf) sg = 0.f;
            sal[b*TT + t] = sg;
            s += sg;
        }
        red[tid] = s;
        __syncthreads();
        for (int o = 128; o > 0; o >>= 1) {
            if (tid < o) red[tid] += red[tid + o];
            __syncthreads();
        }
        if (tid == 0) {
            g_numpred[b] = red[0];
            s_scale[b] = (float)g_nt[b] / red[0];
        }
        __syncthreads();
    }
    // apply scale + zero slast
    for (int i = tid; i < BB*TT; i += 256) sal[i] *= s_scale[i / TT];
    for (int i = tid; i < BB*(NTOK+1); i += 256) slast[i] = 0;
    __syncthreads();

    // ---- phase B: exact scan (lanes 0..15)
    if (tid < BB) {
        const unsigned FULL = 0xFFFFu;
        int b = tid;
        float integrate = 0.f, prem = 0.f;
        int idx = 0;
        int nt1 = g_nt[b] - 1;
        int base = b * MAXP;
        int pcnt = 0;
        const float* al = sal + b*TT;
        int* lrow = slast + b*(NTOK+1);

        // fast-path buffer (common: exactly one .set entry per frame)
        int pn0 = 0; float pw0 = 0.f;
        // slow-path buffer
        int pn[6]; float pw[6]; int pc = 0; bool slowprev = false;

        for (int t = 0; t < TT; t++) {
            if (t > 0) {
                if (!slowprev) {
                    if (pw0 != 0.f && pcnt < MAXP) {
                        g_pairs[base+pcnt] = make_int4(pn0, t-1, __float_as_int(pw0), 0);
                        lrow[pn0] = pcnt + 1; pcnt++;
                    }
                    if (prem != 0.f && pcnt < MAXP) {
                        g_pairs[base+pcnt] = make_int4(idx, t-1, __float_as_int(prem), 0);
                        lrow[idx] = pcnt + 1; pcnt++;
                    }
                } else {
                    // slow flush: append remainder, then emit buffer
                    if (prem != 0.f) {
                        #pragma unroll
                        for (int j = 0; j < 6; j++)
                            if (j == pc) { pn[j] = idx; pw[j] = prem; }
                        if (pc < 6) pc++;
                    }
                    #pragma unroll
                    for (int i = 0; i < 6; i++) {
                        if (i < pc && pw[i] != 0.f && pcnt < MAXP) {
                            g_pairs[base+pcnt] = make_int4(pn[i], t-1, __float_as_int(pw[i]), 0);
                            lrow[pn[i]] = pcnt + 1; pcnt++;
                        }
                    }
                }
            }
            float a = al[t];
            float an = 1.f - integrate;
            integrate += a;
            bool ready = (integrate >= 1.f);
            if (ready) integrate -= 1.f;
            float aint = ready ? an : a;
            pn0 = idx; pw0 = aint;
            prem = a - aint;
            if (ready) idx = min(idx + 1, nt1);
            slowprev = false;
            pc = 0;

            #pragma unroll
            for (int e = 0; e < 3; e++) {
                bool any = __any_sync(FULL, integrate >= 1.f);   // warp-uniform
                if (any) {
                    if (!slowprev) { pn[0] = pn0; pw[0] = pw0; pc = 1; slowprev = true; }
                    bool r2 = (integrate >= 1.f);
                    if (r2) integrate -= 1.f;
                    float ai2 = r2 ? 1.f : prem;
                    bool found = false;
                    #pragma unroll
                    for (int j = 0; j < 6; j++)
                        if (j < pc && pn[j] == idx && !found) { pw[j] = ai2; found = true; }
                    if (!found) {
                        #pragma unroll
                        for (int j = 0; j < 6; j++)
                            if (j == pc) { pn[j] = idx; pw[j] = ai2; }
                        if (pc < 6) pc++;
                    }
                    prem = prem - ai2;
                    if (r2) idx = min(idx + 1, nt1);
                }
            }
        }
        // final frame T-1: flush WITHOUT its remainder
        if (!slowprev) {
            if (pw0 != 0.f && pcnt < MAXP) {
                g_pairs[base+pcnt] = make_int4(pn0, TT-1, __float_as_int(pw0), 0);
                lrow[pn0] = pcnt + 1; pcnt++;
            }
        } else {
            #pragma unroll
            for (int i = 0; i < 6; i++) {
                if (i < pc && pw[i] != 0.f && pcnt < MAXP) {
                    g_pairs[base+pcnt] = make_int4(pn[i], TT-1, __float_as_int(pw[i]), 0);
                    lrow[pn[i]] = pcnt + 1; pcnt++;
                }
            }
        }
        // rowptr from last-emission table (monotone where nonzero)
        int* rp = &g_rowptr[b*(NTOK+1)];
        rp[0] = 0;
        int p = 0;
        for (int n = 0; n < NTOK; n++) {
            int v = lrow[n];
            if (v > 0) p = v;
            rp[n+1] = p;
        }
    }
}

// ---------------------------------------------------------------------------
// Kernel 3: h1 = CIF sparse sum, written as fp16 hi/lo splits
// ---------------------------------------------------------------------------
__global__ void k_h1(const float* __restrict__ af) {
    int r = blockIdx.x;
    int b = r / NTOK, n = r % NTOK;
    int s = g_rowptr[b*(NTOK+1) + n];
    int e = g_rowptr[b*(NTOK+1) + n + 1];
    int d = threadIdx.x;
    float a0 = 0.f, a1 = 0.f, a2 = 0.f, a3 = 0.f;
    for (int p = s; p < e; p++) {
        int4 pr = g_pairs[b*MAXP + p];
        int   t = pr.y;
        float w = __int_as_float(pr.z);
        const float* row = af + ((size_t)b*TT + t)*DD;
        a0 += w * row[d];
        a1 += w * row[d + 256];
        a2 += w * row[d + 512];
        if (d + 768 < DH) a3 += w * row[d + 768];
    }
    size_t o = (size_t)r*LDH;
    __half h, l;
    split_h(a0, h, l); g_ahi[o+d]     = h; g_alo[o+d]     = l;
    split_h(a1, h, l); g_ahi[o+d+256] = h; g_alo[o+d+256] = l;
    split_h(a2, h, l); g_ahi[o+d+512] = h; g_alo[o+d+512] = l;
    if (d + 768 < DH) { split_h(a3, h, l); g_ahi[o+d+768] = h; g_alo[o+d+768] = l; }
    else { g_ahi[o+1023] = __float2half(0.f); g_alo[o+1023] = __float2half(0.f); }
}

// ---------------------------------------------------------------------------
// Kernel 3b: pad cif_w [1024,1023] -> fp16 hi [1024,1024]
// ---------------------------------------------------------------------------
__global__ void k_padw_hi(const float* __restrict__ w) {
    int i = blockIdx.x * 256 + threadIdx.x;
    int n = i >> 10, k = i & 1023;
    float v = (k < DH) ? w[(size_t)n*DH + k] : 0.f;
    g_bhi[i] = __float2half(v);
}

// ---------------------------------------------------------------------------
// Kernel 3c: text_w [4096,1024] -> fp16 hi
// ---------------------------------------------------------------------------
__global__ void k_w_hi(const float* __restrict__ w) {
    int i = blockIdx.x * 256 + threadIdx.x;
    g_bhi[i] = __float2half(w[i]);
}

// ---------------------------------------------------------------------------
// Kernel 5: RMSNorm on g_h2, write normalized rows as fp16 hi only
// ---------------------------------------------------------------------------
__global__ void k_rms(const float* __restrict__ lnw) {
    int r = blockIdx.x;
    const float* hp = g_h2 + (size_t)r*DD;
    int tid = threadIdx.x;
    float v0 = hp[tid], v1 = hp[tid+256], v2 = hp[tid+512], v3 = hp[tid+768];
    __shared__ float red[256];
    red[tid] = v0*v0 + v1*v1 + v2*v2 + v3*v3;
    __syncthreads();
    for (int o = 128; o > 0; o >>= 1) {
        if (tid < o) red[tid] += red[tid + o];
        __syncthreads();
    }
    float inv = rsqrtf(red[0] * (1.0f/DD) + 1e-6f);
    size_t o = (size_t)r*DD;
    g_ahi[o+tid]     = __float2half(v0*inv*lnw[tid]);
    g_ahi[o+tid+256] = __float2half(v1*inv*lnw[tid+256]);
    g_ahi[o+tid+512] = __float2half(v2*inv*lnw[tid+512]);
    g_ahi[o+tid+768] = __float2half(v3*inv*lnw[tid+768]);
}

// ---------------------------------------------------------------------------
// fp16 tensor-core GEMM (mma.sync.m16n8k16, pre-split operands).
// NPASS=2: C = Ah·Bh + Al·Bh ; NPASS=1: C = Ah·Bh
// 128x128 CTA tile, BK=32, 256 threads, warp tile 64x32.
// ---------------------------------------------------------------------------
#define ASTRIDE   40                       // smem row stride in halves (80 B)
#define TILEB     (128*ASTRIDE*2)          // 10240 B per operand-part tile

__device__ __forceinline__ void cp16(uint32_t dst, const void* src) {
    asm volatile("cp.async.cg.shared.global [%0], [%1], 16;"
                 :: "r"(dst), "l"(src) : "memory");
}
__device__ __forceinline__ void ldsm4(uint32_t r[4], uint32_t addr) {
    asm volatile("ldmatrix.sync.aligned.m8n8.x4.shared.b16 {%0,%1,%2,%3}, [%4];"
                 : "=r"(r[0]), "=r"(r[1]), "=r"(r[2]), "=r"(r[3]) : "r"(addr));
}
__device__ __forceinline__ void mma_h(float d[4], const uint32_t a[4],
                                      uint32_t b0, uint32_t b1) {
    asm volatile(
        "mma.sync.aligned.m16n8k16.row.col.f32.f16.f16.f32 "
        "{%0,%1,%2,%3}, {%4,%5,%6,%7}, {%8,%9}, {%0,%1,%2,%3};"
        : "+f"(d[0]), "+f"(d[1]), "+f"(d[2]), "+f"(d[3])
        : "r"(a[0]), "r"(a[1]), "r"(a[2]), "r"(a[3]), "r"(b0), "r"(b1));
}

template<int NPASS>   // 1: A plain; 2: A hi/lo split
__global__ void __launch_bounds__(256)
gemm_h(int M, int K,
       const __half* __restrict__ Ah, const __half* __restrict__ Al, int lda,
       const __half* __restrict__ Bh, int ldb,
       const float* __restrict__ bias,
       float* __restrict__ C, int ldc)
{
    constexpr int NA = (NPASS == 2) ? 2 : 1;
    constexpr int NTILES = NA + 1;
    constexpr uint32_t STAGEB = NTILES * TILEB;
    extern __shared__ __align__(128) char smem[];
    uint32_t sbase = (uint32_t)__cvta_generic_to_shared(smem);

    int tid  = threadIdx.x;
    int wid  = tid >> 5, lane = tid & 31;
    int g    = lane >> 2, tig = lane & 3;
    int m0   = blockIdx.y * 128;
    int n0   = blockIdx.x * 128;
    int wm   = (wid & 1) * 64;
    int wn   = (wid >> 1) * 32;

    float acc[4][4][4];
    #pragma unroll
    for (int i = 0; i < 4; i++)
        #pragma unroll
        for (int j = 0; j < 4; j++)
            #pragma unroll
            for (int q = 0; q < 4; q++) acc[i][j][q] = 0.f;

    const int nt = K >> 5;

    auto load_stage = [&](int s, int kt) {
        uint32_t st = sbase + (uint32_t)s * STAGEB;
        int k0 = kt << 5;
        #pragma unroll
        for (int c = tid; c < 512; c += 256) {
            int row = c >> 2, ch = (c & 3) << 4;
            int ke = k0 + (ch >> 1);
            int gm = m0 + row; if (gm >= M) gm = M - 1;
            uint32_t d = st + row*80 + ch;
            cp16(d, Ah + (size_t)gm*lda + ke);
            if (NPASS == 2) cp16(d + TILEB, Al + (size_t)gm*lda + ke);
            size_t gb = (size_t)(n0 + row)*ldb + ke;
            cp16(d + NA*TILEB, Bh + gb);
        }
        asm volatile("cp.async.commit_group;" ::: "memory");
    };

    load_stage(0, 0);

    int quad = lane >> 3, qr = lane & 7;
    for (int kt = 0; kt < nt; kt++) {
        int buf = kt & 1;
        if (kt + 1 < nt) {
            load_stage(buf ^ 1, kt + 1);
            asm volatile("cp.async.wait_group 1;" ::: "memory");
        } else {
            asm volatile("cp.async.wait_group 0;" ::: "memory");
        }
        __syncthreads();

        uint32_t st = sbase + (uint32_t)buf * STAGEB;
        #pragma unroll
        for (int ks = 0; ks < 2; ks++) {
            int kc = ks * 16;
            uint32_t ka = (uint32_t)((kc + ((quad >> 1) << 3)) << 1);
            uint32_t arow = st + (uint32_t)(wm + ((quad & 1) << 3) + qr) * 80 + ka;
            uint32_t brow = st + NA*TILEB
                          + (uint32_t)(wn + ((quad & 1) << 3) + qr) * 80 + ka;

            uint32_t ah[4][4], al[4][4], bh[2][4];
            #pragma unroll
            for (int mi = 0; mi < 4; mi++) {
                ldsm4(ah[mi], arow + mi*16*80);
                if (NPASS == 2) ldsm4(al[mi], arow + TILEB + mi*16*80);
            }
            #pragma unroll
            for (int nb = 0; nb < 2; nb++)
                ldsm4(bh[nb], brow + nb*16*80);

            #pragma unroll
            for (int mi = 0; mi < 4; mi++)
                #pragma unroll
                for (int ni = 0; ni < 4; ni++) {
                    int nb = ni >> 1, sel = ni & 1;
                    mma_h(acc[mi][ni], ah[mi], bh[nb][sel], bh[nb][sel+2]);
                    if (NPASS == 2)
                        mma_h(acc[mi][ni], al[mi], bh[nb][sel], bh[nb][sel+2]);
                }
        }
        __syncthreads();
    }

    #pragma unroll
    for (int mi = 0; mi < 4; mi++) {
        int row0 = m0 + wm + mi*16 + g;
        int row1 = row0 + 8;
        #pragma unroll
        for (int ni = 0; ni < 4; ni++) {
            int col = n0 + wn + ni*8 + 2*tig;
            float b0 = bias[col], b1 = bias[col+1];
            if (row0 < M) {
                float2 v = { acc[mi][ni][0] + b0, acc[mi][ni][1] + b1 };
                *reinterpret_cast<float2*>(C + (size_t)row0*ldc + col) = v;
            }
            if (row1 < M) {
                float2 v = { acc[mi][ni][2] + b0, acc[mi][ni][3] + b1 };
                *reinterpret_cast<float2*>(C + (size_t)row1*ldc + col) = v;
            }
        }
    }
}

// ---------------------------------------------------------------------------
// Kernel 7: optional tail outputs
// ---------------------------------------------------------------------------
__global__ void k_tail(float* __restrict__ out, int out_size) {
    int i = threadIdx.x;
    if (i < BB && out_size >= MM*DTXT + 2*BB) {
        out[MM*DTXT + i]      = (float)g_nt[i];
        out[MM*DTXT + BB + i] = g_numpred[i];
    }
}

// ---------------------------------------------------------------------------
extern "C" void kernel_launch(void* const* d_in, const int* in_sizes, int n_in,
                              void* d_out, int out_size) {
    const float* af     = (const float*)d_in[0];
    const float* cif_w  = (const float*)d_in[1];
    const float* cif_b  = (const float*)d_in[2];
    const float* ln_w   = (const float*)d_in[3];
    const float* text_w = (const float*)d_in[4];
    const float* text_b = (const float*)d_in[5];
    const void*  nf     = d_in[6];
    const void*  nt     = d_in[7];
    float* out = (float*)d_out;

    void *p_h2=0, *p_ahi=0, *p_alo=0, *p_bhi=0;
    cudaGetSymbolAddress(&p_h2,  g_h2);
    cudaGetSymbolAddress(&p_ahi, g_ahi);
    cudaGetSymbolAddress(&p_alo, g_alo);
    cudaGetSymbolAddress(&p_bhi, g_bhi);

    const int SMEM2 = 2 * 3 * TILEB;   // 61440 (A split)
    const int SMEM1 = 2 * 2 * TILEB;   // 40960 (A plain)
    cudaFuncSetAttribute(gemm_h<2>, cudaFuncAttributeMaxDynamicSharedMemorySize, SMEM2);
    cudaFuncSetAttribute(gemm_h<1>, cudaFuncAttributeMaxDynamicSharedMemorySize, SMEM1);
    cudaFuncSetAttribute(k_cif3,    cudaFuncAttributeMaxDynamicSharedMemorySize, CIF_SMEM);

    k_detect<<<1, 1>>>(nf, nt);
    k_cif3<<<1, 256, CIF_SMEM>>>(af);
    k_h1<<<MM, 256>>>(af);                          // -> g_ahi/g_alo (fp16)
    k_padw_hi<<<(DD*DD)/256, 256>>>(cif_w);         // -> g_bhi (fp16)

    // cif_proj: 2-pass (A split, B fp16): [6000,1024] x [1024,1024]^T -> g_h2
    {
        dim3 grid(DD/128, (MM + 127)/128);
        gemm_h<2><<<grid, 256, SMEM2>>>(MM, 1024,
            (const __half*)p_ahi, (const __half*)p_alo, LDH,
            (const __half*)p_bhi, 1024,
            cif_b, (float*)p_h2, DD);
    }
    k_rms<<<MM, 256>>>(ln_w);                       // g_h2 -> g_ahi (hi only)
    k_w_hi<<<(DTXT*DD)/256, 256>>>(text_w);         // -> g_bhi

    // text_proj: 1-pass fp16: [6000,1024] x [4096,1024]^T -> out
    {
        dim3 grid(DTXT/128, (MM + 127)/128);
        gemm_h<1><<<grid, 256, SMEM1>>>(MM, 1024,
            (const __half*)p_ahi, (const __half*)p_alo, DD,
            (const __half*)p_bhi, DD,
            text_b, out, DTXT);
    }
    k_tail<<<1, 32>>>(out, out_size);
}

// round 10
// speedup vs baseline: 7.6430x; 1.6499x over previous
#include <cuda_runtime.h>
#include <cuda_fp16.h>
#include <math.h>
#include <stdint.h>

// ---------------------------------------------------------------------------
// Problem dimensions (fixed by the dataset)
// ---------------------------------------------------------------------------
#define BB   16
#define TT   1500
#define DD   1024
#define DH   1023
#define DTXT 4096
#define NTOK 375
#define MM   (BB*NTOK)     // 6000
#define MAXP 12288
#define LDH  1024

// ---------------------------------------------------------------------------
// Device scratch
// ---------------------------------------------------------------------------
__device__ float g_numpred[BB];
__device__ int   g_nf[BB];
__device__ int   g_nt[BB];
__device__ int2  g_pairs[BB*MAXP];              // {t, w_bits}; n implied by rowptr
__device__ int   g_rowptr[BB*(NTOK+1)];
__device__ float g_h2 [(size_t)MM*DD];          // cif_proj out
__device__ __half g_ahi[(size_t)MM*LDH];        // A hi
__device__ __half g_alo[(size_t)MM*LDH];        // A lo (cif_proj only)
__device__ __half g_bhi[(size_t)DTXT*DD];       // B hi

// ---------------------------------------------------------------------------
// fp16 split: x = hi + lo + O(2^-22 x)
// ---------------------------------------------------------------------------
__device__ __forceinline__ void split_h(float x, __half& h, __half& l) {
    h = __float2half(x);
    l = __float2half(x - __half2float(h));
}

// ---------------------------------------------------------------------------
// Kernel 0: int64/int32 detection
// ---------------------------------------------------------------------------
__global__ void k_detect(const void* nf_raw, const void* nt_raw) {
    const int* a = (const int*)nf_raw;
    const int* b = (const int*)nt_raw;
    bool is64 = (a[1] == 0) && (a[3] == 0) && (a[5] == 0);
    for (int i = 0; i < BB; i++) {
        if (is64) {
            g_nf[i] = (int)((const long long*)nf_raw)[i];
            g_nt[i] = (int)((const long long*)nt_raw)[i];
        } else {
            g_nf[i] = a[i];
            g_nt[i] = b[i];
        }
    }
}

// ---------------------------------------------------------------------------
// Kernel CIF v4: fused alphas (16 warps, one per batch) + vote-free exact
// scan (warp 0, lanes 0..15) with slow-path fallback (never taken: scaled
// alphas < 1 implies at most one fire per frame).
// ---------------------------------------------------------------------------
#define CIF_SMEM (BB*TT*4 + BB*(NTOK+1)*4)   // 96000 + 24064 = 120064 B

__global__ void __launch_bounds__(512) k_cif4(const float* __restrict__ af) {
    extern __shared__ char cs[];
    float* sal   = (float*)cs;                  // [BB*TT]
    int*   slast = (int*)(cs + BB*TT*4);        // [BB*(NTOK+1)]
    int tid = threadIdx.x;
    int w = tid >> 5, lane = tid & 31;

    // ---- phase A: warp w handles batch w ----
    {
        int b = w;
        int nf = g_nf[b];
        float s = 0.f;
        for (int t = lane; t < TT; t += 32) {
            float x  = af[((size_t)b*TT + t)*DD + (DD-1)];
            float sg = 1.0f / (1.0f + expf(-x));
            if (t >= nf) sg = 0.f;
            sal[b*TT + t] = sg;
            s += sg;
        }
        #pragma unroll
        for (int o = 16; o > 0; o >>= 1)
            s += __shfl_xor_sync(0xFFFFFFFFu, s, o);
        if (lane == 0) g_numpred[b] = s;
        float scale = (float)g_nt[b] / s;
        for (int t = lane; t < TT; t += 32)
            sal[b*TT + t] *= scale;
    }
    __syncthreads();
    for (int i = tid; i < BB*(NTOK+1); i += 512) slast[i] = 0;
    __syncthreads();

    // ---- phase B: exact scan (warp 0, lanes 0..15) ----
    if (tid < BB) {
        const unsigned FULL = 0xFFFFu;
        int b = tid;
        const float* al = sal + b*TT;
        int* lrow = slast + b*(NTOK+1);
        int base = b * MAXP;
        int nt1 = g_nt[b] - 1;

        float integrate = 0.f;
        int idx = 0, pcnt = 0;
        float p_w0 = 0.f, p_w1 = 0.f;
        int   p_n0 = 0,   p_n1 = 0;
        bool  efire = false;

        #pragma unroll 4
        for (int t = 0; t < TT; t++) {
            float a = al[t];
            // flush frame t-1 (predicated, <=2 pairs; pairs sorted by n)
            if (t > 0) {
                if (p_w0 != 0.f) {
                    g_pairs[base+pcnt] = make_int2(t-1, __float_as_int(p_w0));
                    lrow[p_n0] = ++pcnt;
                }
                if (p_w1 != 0.f) {
                    g_pairs[base+pcnt] = make_int2(t-1, __float_as_int(p_w1));
                    lrow[p_n1] = ++pcnt;
                }
            }
            float an = 1.f - integrate;
            integrate += a;
            bool ready = (integrate >= 1.f);
            float aint = ready ? an : a;
            if (ready) integrate -= 1.f;
            p_n0 = idx; p_w0 = aint;
            p_w1 = a - aint;                 // nonzero only when fired
            if (ready) idx = min(idx + 1, nt1);
            p_n1 = idx;
            efire |= (integrate >= 1.f);     // extra-fire condition (never, in practice)
        }
        // final frame T-1: emit set-value only, drop remainder (reference drops it)
        if (p_w0 != 0.f) {
            g_pairs[base+pcnt] = make_int2(TT-1, __float_as_int(p_w0));
            lrow[p_n0] = ++pcnt;
        }

        // ---- slow-path fallback (bit-exact reference semantics w/ votes) ----
        bool slow = __any_sync(FULL, efire);
        if (slow) {
            for (int n = 0; n <= NTOK; n++) lrow[n] = 0;
            integrate = 0.f; idx = 0; pcnt = 0;
            float prem = 0.f;
            int pn[6]; float pw[6]; int pc = 0;
            for (int t = 0; t < TT; t++) {
                if (t > 0) {
                    if (prem != 0.f) {
                        #pragma unroll
                        for (int j = 0; j < 6; j++)
                            if (j == pc) { pn[j] = idx; pw[j] = prem; }
                        if (pc < 6) pc++;
                    }
                    #pragma unroll
                    for (int i = 0; i < 6; i++) {
                        if (i < pc && pw[i] != 0.f && pcnt < MAXP) {
                            g_pairs[base+pcnt] = make_int2(t-1, __float_as_int(pw[i]));
                            lrow[pn[i]] = pcnt + 1; pcnt++;
                        }
                    }
                    pc = 0;
                }
                float a = al[t];
                float an = 1.f - integrate;
                integrate += a;
                bool ready = (integrate >= 1.f);
                if (ready) integrate -= 1.f;
                float aint = ready ? an : a;
                pn[0] = idx; pw[0] = aint; pc = 1;
                prem = a - aint;
                if (ready) idx = min(idx + 1, nt1);
                #pragma unroll
                for (int e = 0; e < 3; e++) {
                    bool any = __any_sync(FULL, integrate >= 1.f);
                    if (any) {
                        bool r2 = (integrate >= 1.f);
                        if (r2) integrate -= 1.f;
                        float ai2 = r2 ? 1.f : prem;
                        bool found = false;
                        #pragma unroll
                        for (int j = 0; j < 6; j++)
                            if (j < pc && pn[j] == idx && !found) { pw[j] = ai2; found = true; }
                        if (!found) {
                            #pragma unroll
                            for (int j = 0; j < 6; j++)
                                if (j == pc) { pn[j] = idx; pw[j] = ai2; }
                            if (pc < 6) pc++;
                        }
                        prem = prem - ai2;
                        if (r2) idx = min(idx + 1, nt1);
                    }
                }
            }
            #pragma unroll
            for (int i = 0; i < 6; i++) {
                if (i < pc && pw[i] != 0.f && pcnt < MAXP) {
                    g_pairs[base+pcnt] = make_int2(TT-1, __float_as_int(pw[i]));
                    lrow[pn[i]] = pcnt + 1; pcnt++;
                }
            }
        } else {
            __any_sync(FULL, false);   // keep lanes converged
        }

        // rowptr from last-emission table
        int* rp = &g_rowptr[b*(NTOK+1)];
        rp[0] = 0;
        int p = 0;
        for (int n = 0; n < NTOK; n++) {
            int v = lrow[n];
            if (v > 0) p = v;
            rp[n+1] = p;
        }
    }
}

// ---------------------------------------------------------------------------
// Kernel 3: h1 = CIF sparse sum, written as fp16 hi/lo splits
// ---------------------------------------------------------------------------
__global__ void k_h1(const float* __restrict__ af) {
    int r = blockIdx.x;
    int b = r / NTOK, n = r % NTOK;
    int s = g_rowptr[b*(NTOK+1) + n];
    int e = g_rowptr[b*(NTOK+1) + n + 1];
    int d = threadIdx.x;
    float a0 = 0.f, a1 = 0.f, a2 = 0.f, a3 = 0.f;
    for (int p = s; p < e; p++) {
        int2 pr = g_pairs[b*MAXP + p];
        int   t = pr.x;
        float w = __int_as_float(pr.y);
        const float* row = af + ((size_t)b*TT + t)*DD;
        a0 += w * row[d];
        a1 += w * row[d + 256];
        a2 += w * row[d + 512];
        if (d + 768 < DH) a3 += w * row[d + 768];
    }
    size_t o = (size_t)r*LDH;
    __half h, l;
    split_h(a0, h, l); g_ahi[o+d]     = h; g_alo[o+d]     = l;
    split_h(a1, h, l); g_ahi[o+d+256] = h; g_alo[o+d+256] = l;
    split_h(a2, h, l); g_ahi[o+d+512] = h; g_alo[o+d+512] = l;
    if (d + 768 < DH) { split_h(a3, h, l); g_ahi[o+d+768] = h; g_alo[o+d+768] = l; }
    else { g_ahi[o+1023] = __float2half(0.f); g_alo[o+1023] = __float2half(0.f); }
}

// ---------------------------------------------------------------------------
// Kernel 3b: pad cif_w [1024,1023] -> fp16 hi [1024,1024]
// ---------------------------------------------------------------------------
__global__ void k_padw_hi(const float* __restrict__ w) {
    int i = blockIdx.x * 256 + threadIdx.x;
    int n = i >> 10, k = i & 1023;
    float v = (k < DH) ? w[(size_t)n*DH + k] : 0.f;
    g_bhi[i] = __float2half(v);
}

// ---------------------------------------------------------------------------
// Kernel 3c: text_w [4096,1024] -> fp16 hi
// ---------------------------------------------------------------------------
__global__ void k_w_hi(const float* __restrict__ w) {
    int i = blockIdx.x * 256 + threadIdx.x;
    g_bhi[i] = __float2half(w[i]);
}

// ---------------------------------------------------------------------------
// Kernel 5: RMSNorm on g_h2, write normalized rows as fp16 hi only
// ---------------------------------------------------------------------------
__global__ void k_rms(const float* __restrict__ lnw) {
    int r = blockIdx.x;
    const float* hp = g_h2 + (size_t)r*DD;
    int tid = threadIdx.x;
    float v0 = hp[tid], v1 = hp[tid+256], v2 = hp[tid+512], v3 = hp[tid+768];
    __shared__ float red[256];
    red[tid] = v0*v0 + v1*v1 + v2*v2 + v3*v3;
    __syncthreads();
    for (int o = 128; o > 0; o >>= 1) {
        if (tid < o) red[tid] += red[tid + o];
        __syncthreads();
    }
    float inv = rsqrtf(red[0] * (1.0f/DD) + 1e-6f);
    size_t o = (size_t)r*DD;
    g_ahi[o+tid]     = __float2half(v0*inv*lnw[tid]);
    g_ahi[o+tid+256] = __float2half(v1*inv*lnw[tid+256]);
    g_ahi[o+tid+512] = __float2half(v2*inv*lnw[tid+512]);
    g_ahi[o+tid+768] = __float2half(v3*inv*lnw[tid+768]);
}

// ---------------------------------------------------------------------------
// fp16 tensor-core GEMM (mma.sync.m16n8k16, pre-split operands).
// NPASS=2: C = Ah·Bh + Al·Bh ; NPASS=1: C = Ah·Bh
// 128x128 CTA tile, BK=32, 256 threads, warp tile 64x32.
// ---------------------------------------------------------------------------
#define ASTRIDE   40                       // smem row stride in halves (80 B)
#define TILEB     (128*ASTRIDE*2)          // 10240 B per operand-part tile

__device__ __forceinline__ void cp16(uint32_t dst, const void* src) {
    asm volatile("cp.async.cg.shared.global [%0], [%1], 16;"
                 :: "r"(dst), "l"(src) : "memory");
}
__device__ __forceinline__ void ldsm4(uint32_t r[4], uint32_t addr) {
    asm volatile("ldmatrix.sync.aligned.m8n8.x4.shared.b16 {%0,%1,%2,%3}, [%4];"
                 : "=r"(r[0]), "=r"(r[1]), "=r"(r[2]), "=r"(r[3]) : "r"(addr));
}
__device__ __forceinline__ void mma_h(float d[4], const uint32_t a[4],
                                      uint32_t b0, uint32_t b1) {
    asm volatile(
        "mma.sync.aligned.m16n8k16.row.col.f32.f16.f16.f32 "
        "{%0,%1,%2,%3}, {%4,%5,%6,%7}, {%8,%9}, {%0,%1,%2,%3};"
        : "+f"(d[0]), "+f"(d[1]), "+f"(d[2]), "+f"(d[3])
        : "r"(a[0]), "r"(a[1]), "r"(a[2]), "r"(a[3]), "r"(b0), "r"(b1));
}

template<int NPASS>   // 1: A plain; 2: A hi/lo split
__global__ void __launch_bounds__(256)
gemm_h(int M, int K,
       const __half* __restrict__ Ah, const __half* __restrict__ Al, int lda,
       const __half* __restrict__ Bh, int ldb,
       const float* __restrict__ bias,
       float* __restrict__ C, int ldc)
{
    constexpr int NA = (NPASS == 2) ? 2 : 1;
    constexpr int NTILES = NA + 1;
    constexpr uint32_t STAGEB = NTILES * TILEB;
    extern __shared__ __align__(128) char smem[];
    uint32_t sbase = (uint32_t)__cvta_generic_to_shared(smem);

    int tid  = threadIdx.x;
    int wid  = tid >> 5, lane = tid & 31;
    int g    = lane >> 2, tig = lane & 3;
    int m0   = blockIdx.y * 128;
    int n0   = blockIdx.x * 128;
    int wm   = (wid & 1) * 64;
    int wn   = (wid >> 1) * 32;

    float acc[4][4][4];
    #pragma unroll
    for (int i = 0; i < 4; i++)
        #pragma unroll
        for (int j = 0; j < 4; j++)
            #pragma unroll
            for (int q = 0; q < 4; q++) acc[i][j][q] = 0.f;

    const int nt = K >> 5;

    auto load_stage = [&](int s, int kt) {
        uint32_t st = sbase + (uint32_t)s * STAGEB;
        int k0 = kt << 5;
        #pragma unroll
        for (int c = tid; c < 512; c += 256) {
            int row = c >> 2, ch = (c & 3) << 4;
            int ke = k0 + (ch >> 1);
            int gm = m0 + row; if (gm >= M) gm = M - 1;
            uint32_t d = st + row*80 + ch;
            cp16(d, Ah + (size_t)gm*lda + ke);
            if (NPASS == 2) cp16(d + TILEB, Al + (size_t)gm*lda + ke);
            size_t gb = (size_t)(n0 + row)*ldb + ke;
            cp16(d + NA*TILEB, Bh + gb);
        }
        asm volatile("cp.async.commit_group;" ::: "memory");
    };

    load_stage(0, 0);

    int quad = lane >> 3, qr = lane & 7;
    for (int kt = 0; kt < nt; kt++) {
        int buf = kt & 1;
        if (kt + 1 < nt) {
            load_stage(buf ^ 1, kt + 1);
            asm volatile("cp.async.wait_group 1;" ::: "memory");
        } else {
            asm volatile("cp.async.wait_group 0;" ::: "memory");
        }
        __syncthreads();

        uint32_t st = sbase + (uint32_t)buf * STAGEB;
        #pragma unroll
        for (int ks = 0; ks < 2; ks++) {
            int kc = ks * 16;
            uint32_t ka = (uint32_t)((kc + ((quad >> 1) << 3)) << 1);
            uint32_t arow = st + (uint32_t)(wm + ((quad & 1) << 3) + qr) * 80 + ka;
            uint32_t brow = st + NA*TILEB
                          + (uint32_t)(wn + ((quad & 1) << 3) + qr) * 80 + ka;

            uint32_t ah[4][4], al[4][4], bh[2][4];
            #pragma unroll
            for (int mi = 0; mi < 4; mi++) {
                ldsm4(ah[mi], arow + mi*16*80);
                if (NPASS == 2) ldsm4(al[mi], arow + TILEB + mi*16*80);
            }
            #pragma unroll
            for (int nb = 0; nb < 2; nb++)
                ldsm4(bh[nb], brow + nb*16*80);

            #pragma unroll
            for (int mi = 0; mi < 4; mi++)
                #pragma unroll
                for (int ni = 0; ni < 4; ni++) {
                    int nb = ni >> 1, sel = ni & 1;
                    mma_h(acc[mi][ni], ah[mi], bh[nb][sel], bh[nb][sel+2]);
                    if (NPASS == 2)
                        mma_h(acc[mi][ni], al[mi], bh[nb][sel], bh[nb][sel+2]);
                }
        }
        __syncthreads();
    }

    #pragma unroll
    for (int mi = 0; mi < 4; mi++) {
        int row0 = m0 + wm + mi*16 + g;
        int row1 = row0 + 8;
        #pragma unroll
        for (int ni = 0; ni < 4; ni++) {
            int col = n0 + wn + ni*8 + 2*tig;
            float b0 = bias[col], b1 = bias[col+1];
            if (row0 < M) {
                float2 v = { acc[mi][ni][0] + b0, acc[mi][ni][1] + b1 };
                *reinterpret_cast<float2*>(C + (size_t)row0*ldc + col) = v;
            }
            if (row1 < M) {
                float2 v = { acc[mi][ni][2] + b0, acc[mi][ni][3] + b1 };
                *reinterpret_cast<float2*>(C + (size_t)row1*ldc + col) = v;
            }
        }
    }
}

// ---------------------------------------------------------------------------
// Kernel 7: optional tail outputs
// ---------------------------------------------------------------------------
__global__ void k_tail(float* __restrict__ out, int out_size) {
    int i = threadIdx.x;
    if (i < BB && out_size >= MM*DTXT + 2*BB) {
        out[MM*DTXT + i]      = (float)g_nt[i];
        out[MM*DTXT + BB + i] = g_numpred[i];
    }
}

// ---------------------------------------------------------------------------
extern "C" void kernel_launch(void* const* d_in, const int* in_sizes, int n_in,
                              void* d_out, int out_size) {
    const float* af     = (const float*)d_in[0];
    const float* cif_w  = (const float*)d_in[1];
    const float* cif_b  = (const float*)d_in[2];
    const float* ln_w   = (const float*)d_in[3];
    const float* text_w = (const float*)d_in[4];
    const float* text_b = (const float*)d_in[5];
    const void*  nf     = d_in[6];
    const void*  nt     = d_in[7];
    float* out = (float*)d_out;

    void *p_h2=0, *p_ahi=0, *p_alo=0, *p_bhi=0;
    cudaGetSymbolAddress(&p_h2,  g_h2);
    cudaGetSymbolAddress(&p_ahi, g_ahi);
    cudaGetSymbolAddress(&p_alo, g_alo);
    cudaGetSymbolAddress(&p_bhi, g_bhi);

    const int SMEM2 = 2 * 3 * TILEB;   // 61440 (A split)
    const int SMEM1 = 2 * 2 * TILEB;   // 40960 (A plain)
    cudaFuncSetAttribute(gemm_h<2>, cudaFuncAttributeMaxDynamicSharedMemorySize, SMEM2);
    cudaFuncSetAttribute(gemm_h<1>, cudaFuncAttributeMaxDynamicSharedMemorySize, SMEM1);
    cudaFuncSetAttribute(k_cif4,    cudaFuncAttributeMaxDynamicSharedMemorySize, CIF_SMEM);

    k_detect<<<1, 1>>>(nf, nt);
    k_cif4<<<1, 512, CIF_SMEM>>>(af);
    k_h1<<<MM, 256>>>(af);                          // -> g_ahi/g_alo (fp16)
    k_padw_hi<<<(DD*DD)/256, 256>>>(cif_w);         // -> g_bhi (fp16)

    // cif_proj: 2-pass (A split, B fp16): [6000,1024] x [1024,1024]^T -> g_h2
    {
        dim3 grid(DD/128, (MM + 127)/128);
        gemm_h<2><<<grid, 256, SMEM2>>>(MM, 1024,
            (const __half*)p_ahi, (const __half*)p_alo, LDH,
            (const __half*)p_bhi, 1024,
            cif_b, (float*)p_h2, DD);
    }
    k_rms<<<MM, 256>>>(ln_w);                       // g_h2 -> g_ahi (hi only)
    k_w_hi<<<(DTXT*DD)/256, 256>>>(text_w);         // -> g_bhi

    // text_proj: 1-pass fp16: [6000,1024] x [4096,1024]^T -> out
    {
        dim3 grid(DTXT/128, (MM + 127)/128);
        gemm_h<1><<<grid, 256, SMEM1>>>(MM, 1024,
            (const __half*)p_ahi, (const __half*)p_alo, DD,
            (const __half*)p_bhi, DD,
            text_b, out, DTXT);
    }
    k_tail<<<1, 32>>>(out, out_size);
}